// round 13
// baseline (speedup 1.0000x reference)
#include <cuda_runtime.h>
#include <math.h>

#define Bn 2
#define Tn 1536
#define Dn 1536
#define Hn 8
#define Kn 64
#define Vn 192
#define HK 512
#define HV 1536
#define Rn 3071

// ---------------- scratch ------------------------------------------------------
__device__ float g_emb[(size_t)Rn * 192];
__device__ unsigned g_gmax_bits;
__device__ float g_q[(size_t)Bn * Tn * HK];        // std layout, tf32
__device__ float g_kp[(size_t)Bn * Hn * Tn * 68];  // [(b*8+h)*T+t][68 pitch], tf32
__device__ float g_rkp[(size_t)Hn * Rn * 68];      // [h*3071+m][68 pitch], tf32
__device__ float g_vp[(size_t)Bn * Hn * Tn * 200]; // [(b*8+h)*T+t][200 pitch], tf32
__device__ float g_att[(size_t)Bn * Tn * HV];
__device__ float g_c1[8 * 3072];
__device__ float g_c2[8 * 3072];

// ---------------- helpers ------------------------------------------------------
__device__ __forceinline__ unsigned f2tf(float x) {
    unsigned u; asm("cvt.rna.tf32.f32 %0, %1;" : "=r"(u) : "f"(x)); return u;
}
__device__ __forceinline__ void mma8(float d[4], const unsigned a[4], const unsigned b[2]) {
    asm volatile(
        "mma.sync.aligned.m16n8k8.row.col.f32.tf32.tf32.f32 "
        "{%0,%1,%2,%3}, {%4,%5,%6,%7}, {%8,%9}, {%0,%1,%2,%3};"
        : "+f"(d[0]), "+f"(d[1]), "+f"(d[2]), "+f"(d[3])
        : "r"(a[0]), "r"(a[1]), "r"(a[2]), "r"(a[3]), "r"(b[0]), "r"(b[1]));
}
#define MBAR_INIT(mb, cnt) \
    asm volatile("mbarrier.init.shared.b64 [%0], %1;" :: "r"(mb), "r"(cnt) : "memory")
#define MBAR_EXPECT_TX(mb, bytes) \
    asm volatile("mbarrier.arrive.expect_tx.shared.b64 _, [%0], %1;" :: "r"(mb), "r"(bytes) : "memory")
#define BULK_G2S(dst, src, bytes, mb) \
    asm volatile("cp.async.bulk.shared::cluster.global.mbarrier::complete_tx::bytes [%0], [%1], %2, [%3];" \
                 :: "r"(dst), "l"(src), "r"(bytes), "r"(mb) : "memory")
#define MBAR_WAIT(mb, parity) do {                                            \
    unsigned _mb = (mb); unsigned _ph = (parity); unsigned _done;             \
    asm volatile("{\n\t.reg .pred p;\n\t"                                     \
        "mbarrier.try_wait.parity.acquire.cta.shared::cta.b64 p, [%1], %2;\n\t" \
        "selp.b32 %0, 1, 0, p;\n\t}"                                          \
        : "=r"(_done) : "r"(_mb), "r"(_ph) : "memory");                       \
    if (!_done) {                                                             \
        asm volatile("{\n\t.reg .pred P1;\n\t"                                \
            "WL_%=:\n\t"                                                      \
            "mbarrier.try_wait.parity.acquire.cta.shared::cta.b64 P1, [%0], %1, 0x989680;\n\t" \
            "@P1 bra.uni WD_%=;\n\t"                                          \
            "bra.uni WL_%=;\n\t"                                              \
            "WD_%=:\n\t}" :: "r"(_mb), "r"(_ph) : "memory");                  \
    }                                                                         \
} while (0)

// ---------------- positional features ------------------------------------------
__global__ void pos_fill() {
    int idx = blockIdx.x * 256 + threadIdx.x;
    bool ok = idx < Rn * 96;
    int p = 0, c = 0;
    float v = 0.f;
    if (ok) {
        p = idx / 96; c = idx % 96;
        float ap = fabsf((float)(p - (Tn - 1)));
        if (c < 32) {
            float max_range = log2f((float)Tn);
            float hl = exp2f(3.0f + (float)c * (max_range - 3.0f) / 31.0f);
            v = exp2f(-ap / hl);
        } else if (c < 64) {
            float w = exp2f((float)(c - 32 + 1)) - 1.0f;
            v = (w > ap) ? 1.0f : 0.0f;
        } else {
            int i = c - 64;
            float mean = 48.0f * (float)(i + 1);
            float conc = (mean / 24.0f) * (mean / 24.0f);
            float rate = mean * (1.0f / 576.0f);
            float lp = (conc - 1.0f) * logf(ap) - rate * ap
                       - (lgammaf(conc) - conc * logf(rate));
            v = expf(lp) + 1e-8f;
        }
        g_emb[(size_t)p * 192 + c] = v;
    }
    float vg = (ok && c >= 64) ? v : 0.f;
#pragma unroll
    for (int o = 16; o > 0; o >>= 1)
        vg = fmaxf(vg, __shfl_xor_sync(0xffffffffu, vg, o));
    if ((threadIdx.x & 31) == 0)
        atomicMax(&g_gmax_bits, __float_as_uint(vg));
}

__global__ void pos_fin() {
    int idx = blockIdx.x * 256 + threadIdx.x;
    if (idx >= Rn * 96) return;
    int p = idx / 96, c = idx % 96;
    float v = g_emb[(size_t)p * 192 + c];
    if (c >= 64) {
        v = v / __uint_as_float(g_gmax_bits);
        g_emb[(size_t)p * 192 + c] = v;
    }
    float sgn = (p < Tn - 1) ? -1.0f : ((p > Tn - 1) ? 1.0f : 0.0f);
    g_emb[(size_t)p * 192 + 96 + c] = sgn * v;
}

// ---------------- rank-1 bias precompute ----------------------------------------
__global__ __launch_bounds__(64) void bias2_kernel(
    const float* __restrict__ rwb, const float* __restrict__ rrb)
{
    int idx = blockIdx.x;
    int t = threadIdx.x;
    int h = t >> 3, part = t & 7;
    const float* sp;
    const float* bp;
    if (idx < 3072) {
        int b = idx >= Tn;
        int tt = idx - (b ? Tn : 0);
        sp = g_kp + ((size_t)(b * 8 + h) * Tn + tt) * 68 + part * 8;
        bp = rwb + h * 64 + part * 8;
    } else {
        int m = idx - 3072;
        sp = g_rkp + ((size_t)h * Rn + m) * 68 + part * 8;
        bp = rrb + h * 64 + part * 8;
    }
    float s = 0.f;
#pragma unroll
    for (int i = 0; i < 8; i++) s = fmaf(bp[i], sp[i], s);
    s += __shfl_down_sync(0xffffffffu, s, 4, 8);
    s += __shfl_down_sync(0xffffffffu, s, 2, 8);
    s += __shfl_down_sync(0xffffffffu, s, 1, 8);
    if (part == 0) {
        if (idx < 3072) g_c1[h * 3072 + idx] = s;
        else            g_c2[h * 3072 + (idx - 3072)] = s;
    }
}

// ---------------- tf32 GEMM body: double-buffered smem, 1 sync per k-tile -------
// SMODE 0: plain fp32; 2: plain tf32; 3: head-major padded tf32.
// As: [2][128*36], Bs: [2][32*136] in dynamic smem.
#define AS_STAGE 4608
#define BS_STAGE 4352
#define GEMM_SMEM ((2 * (AS_STAGE + BS_STAGE)) * 4)   // 71680 B

template <int SMODE, int HMW, int HMPITCH, int HMT>
__device__ __forceinline__ void gemm_body(
    const float* __restrict__ A, const float* __restrict__ B, float* __restrict__ C,
    int M, int N, int Kd, int lda, int ldb, int ldc,
    int bx, int by, float alpha, unsigned* As, unsigned* Bs)
{
    int tid = threadIdx.x;
    int bm = by * 128, bn = bx * 128;
    int w = tid >> 5, lane = tid & 31;
    int wm = w & 1, wn = w >> 1;
    int lr = lane >> 2, lc = lane & 3;

    int arow0 = tid >> 3;
    int ac4   = (tid & 7) << 2;
    int bc4   = lane << 2;
    bool bvalid = (bn + bc4) < N;
    bool avalid[4];
#pragma unroll
    for (int it = 0; it < 4; it++) avalid[it] = (bm + arow0 + it * 32) < M;

    float4 av[4], bv[4];
    const float4 z4 = make_float4(0.f, 0.f, 0.f, 0.f);
#pragma unroll
    for (int it = 0; it < 4; it++) {
        av[it] = avalid[it] ? *(const float4*)(A + (size_t)(bm + arow0 + it * 32) * lda + ac4) : z4;
        bv[it] = bvalid ? *(const float4*)(B + (size_t)(it * 8 + w) * ldb + bn + bc4) : z4;
    }

    float acc[4][4][4] = {};

    // store stage 0
#pragma unroll
    for (int it = 0; it < 4; it++) {
        unsigned* ap = As + (arow0 + it * 32) * 36 + ac4;
        ap[0] = f2tf(av[it].x); ap[1] = f2tf(av[it].y);
        ap[2] = f2tf(av[it].z); ap[3] = f2tf(av[it].w);
        unsigned* bp = Bs + (it * 8 + w) * 136 + bc4;
        bp[0] = f2tf(bv[it].x); bp[1] = f2tf(bv[it].y);
        bp[2] = f2tf(bv[it].z); bp[3] = f2tf(bv[it].w);
    }
    __syncthreads();

    int NT = Kd >> 5;
    for (int kt = 0; kt < NT; kt++) {
        unsigned* Ac = As + (kt & 1) * AS_STAGE;
        unsigned* Bc = Bs + (kt & 1) * BS_STAGE;
        bool more = (kt + 1) < NT;
        if (more) {
            int k0n = (kt + 1) << 5;
#pragma unroll
            for (int it = 0; it < 4; it++) {
                av[it] = avalid[it] ? *(const float4*)(A + (size_t)(bm + arow0 + it * 32) * lda + k0n + ac4) : z4;
                bv[it] = bvalid ? *(const float4*)(B + (size_t)(k0n + it * 8 + w) * ldb + bn + bc4) : z4;
            }
        }
#pragma unroll
        for (int s = 0; s < 4; s++) {
            int kb = s * 8;
            unsigned afr[4][4];
#pragma unroll
            for (int i = 0; i < 4; i++) {
                int r = wm * 64 + i * 16 + lr;
                afr[i][0] = Ac[r * 36 + kb + lc];
                afr[i][1] = Ac[(r + 8) * 36 + kb + lc];
                afr[i][2] = Ac[r * 36 + kb + 4 + lc];
                afr[i][3] = Ac[(r + 8) * 36 + kb + 4 + lc];
            }
            unsigned bfr[4][2];
#pragma unroll
            for (int j = 0; j < 4; j++) {
                int cc = wn * 32 + j * 8 + lr;
                bfr[j][0] = Bc[(kb + lc) * 136 + cc];
                bfr[j][1] = Bc[(kb + 4 + lc) * 136 + cc];
            }
#pragma unroll
            for (int i = 0; i < 4; i++)
#pragma unroll
                for (int j = 0; j < 4; j++)
                    mma8(acc[i][j], afr[i], bfr[j]);
        }
        if (more) {
            unsigned* An = As + ((kt + 1) & 1) * AS_STAGE;
            unsigned* Bnx = Bs + ((kt + 1) & 1) * BS_STAGE;
#pragma unroll
            for (int it = 0; it < 4; it++) {
                unsigned* ap = An + (arow0 + it * 32) * 36 + ac4;
                ap[0] = f2tf(av[it].x); ap[1] = f2tf(av[it].y);
                ap[2] = f2tf(av[it].z); ap[3] = f2tf(av[it].w);
                unsigned* bp = Bnx + (it * 8 + w) * 136 + bc4;
                bp[0] = f2tf(bv[it].x); bp[1] = f2tf(bv[it].y);
                bp[2] = f2tf(bv[it].z); bp[3] = f2tf(bv[it].w);
            }
            __syncthreads();
        }
    }

#pragma unroll
    for (int i = 0; i < 4; i++) {
        int r0 = bm + wm * 64 + i * 16 + lr;
#pragma unroll
        for (int j = 0; j < 4; j++) {
            int c0 = bn + wn * 32 + j * 8 + lc * 2;
            if (c0 >= N) continue;
#pragma unroll
            for (int half = 0; half < 2; half++) {
                int r = r0 + half * 8;
                if (r >= M) continue;
                float o0 = alpha * acc[i][j][half * 2];
                float o1 = alpha * acc[i][j][half * 2 + 1];
                if (SMODE != 0) {
                    o0 = __uint_as_float(f2tf(o0));
                    o1 = __uint_as_float(f2tf(o1));
                }
                if (SMODE == 0 || SMODE == 2) {
                    *(float2*)(C + (size_t)r * ldc + c0) = make_float2(o0, o1);
                } else {
                    int bb = r / HMT, tt = r % HMT;
                    int hh = c0 / HMW, cc = c0 % HMW;
                    float* p = C + ((size_t)(bb * Hn + hh) * HMT + tt) * HMPITCH + cc;
                    *(float2*)p = make_float2(o0, o1);
                }
            }
        }
    }
}

template <int SMODE, int HMW, int HMPITCH, int HMT>
__global__ __launch_bounds__(256) void tgemm_kernel(
    const float* __restrict__ A, const float* __restrict__ B, float* __restrict__ C,
    int M, int N, int Kd, int lda, int ldb, int ldc, float alpha)
{
    extern __shared__ unsigned dynsm[];
    unsigned* As = dynsm;
    unsigned* Bs = dynsm + 2 * AS_STAGE;
    gemm_body<SMODE, HMW, HMPITCH, HMT>(A, B, C, M, N, Kd, lda, ldb, ldc,
                                        blockIdx.x, blockIdx.y, alpha, As, Bs);
}

// fused q/k/v projections: grid.x 0..3 Q, 4..7 K, 8..19 V
__global__ __launch_bounds__(256) void qkv_kernel(
    const float* __restrict__ x, const float* __restrict__ Wq,
    const float* __restrict__ Wk, const float* __restrict__ Wv)
{
    extern __shared__ unsigned dynsm[];
    unsigned* As = dynsm;
    unsigned* Bs = dynsm + 2 * AS_STAGE;
    int bx = blockIdx.x;
    if (bx < 4) {
        gemm_body<2, 1, 1, 1>(x, Wq, g_q, Bn * Tn, HK, Dn, Dn, HK, HK,
                              bx, blockIdx.y, 0.125f, As, Bs);
    } else if (bx < 8) {
        gemm_body<3, 64, 68, Tn>(x, Wk, g_kp, Bn * Tn, HK, Dn, Dn, HK, 0,
                                 bx - 4, blockIdx.y, 1.0f, As, Bs);
    } else {
        gemm_body<3, 192, 200, Tn>(x, Wv, g_vp, Bn * Tn, HV, Dn, Dn, HV, 0,
                                   bx - 8, blockIdx.y, 1.0f, As, Bs);
    }
}

// ---------------- fused flash attention, bulk-async tiles (R10 champion) -------
#define LDK 68
#define LDV 200
#define LDR 132
#define OFF_K0  0
#define OFF_K1  4352
#define OFF_RK0 8704
#define OFF_RK1 17408
#define OFF_V   26112
#define OFF_REL 38912
#define OFF_PS  47360
#define OFF_RED 51712
#define MBAR_BYTE (51968 * 4)
#define SM_BYTES (51968 * 4 + 32)

#define KT_BYTES  (64 * 68 * 4)
#define RKT_BYTES (127 * 68 * 4)
#define VT_BYTES  (64 * 200 * 4)

__global__ __launch_bounds__(256, 1) void flash_kernel() {
    extern __shared__ float smf[];
    float* Vs  = smf + OFF_V;
    float* rel = smf + OFF_REL;
    float* Ps  = smf + OFF_PS;
    float* smx = smf + OFF_RED;
    float* sms = smx + 128;

    unsigned smb = (unsigned)__cvta_generic_to_shared(smf);
    unsigned mbK0 = smb + MBAR_BYTE, mbK1 = smb + MBAR_BYTE + 8, mbV = smb + MBAR_BYTE + 16;

    int bh = blockIdx.y, b = bh >> 3, h = bh & 7;
    int q0 = blockIdx.x * 64;
    int tid = threadIdx.x, w = tid >> 5, lane = tid & 31;
    int lr = lane >> 2, lc = lane & 3;
    int qw = (w >> 1) * 16;
    int nhalf = w & 1;

    const float* kbaseg  = g_kp  + (size_t)(b * 8 + h) * Tn * 68;
    const float* rkbaseg = g_rkp + (size_t)h * Rn * 68;
    const float* vbaseg  = g_vp  + (size_t)(b * 8 + h) * Tn * 200;

    if (tid == 0) {
        MBAR_INIT(mbK0, 1);
        MBAR_INIT(mbK1, 1);
        MBAR_INIT(mbV, 1);
    }
    if (tid < 68)  smf[OFF_RK0 + 127 * LDK + tid] = 0.f;
    if (tid >= 68 && tid < 136) smf[OFF_RK1 + 127 * LDK + tid - 68] = 0.f;
    __syncthreads();

    if (tid == 0) {
        int mbase = 1472 - q0;
        MBAR_EXPECT_TX(mbK0, KT_BYTES + RKT_BYTES);
        BULK_G2S(smb + OFF_K0 * 4,  kbaseg, KT_BYTES, mbK0);
        BULK_G2S(smb + OFF_RK0 * 4, rkbaseg + (size_t)mbase * 68, RKT_BYTES, mbK0);
    }

    const float* qg = g_q + (size_t)(b * Tn + q0) * HK + h * Kn;
    unsigned qf[8][4];
#pragma unroll
    for (int s = 0; s < 8; s++) {
        int c = s * 8 + lc;
        qf[s][0] = __float_as_uint(qg[(size_t)(qw + lr) * HK + c]);
        qf[s][1] = __float_as_uint(qg[(size_t)(qw + 8 + lr) * HK + c]);
        qf[s][2] = __float_as_uint(qg[(size_t)(qw + lr) * HK + c + 4]);
        qf[s][3] = __float_as_uint(qg[(size_t)(qw + 8 + lr) * HK + c + 4]);
    }

    const float* c1base = g_c1 + h * 3072 + b * Tn;
    const float* c2base = g_c2 + h * 3072;

    float accO[12][4] = {};
    float m_lo = -1e30f, m_hi = -1e30f, l_lo = 0.f, l_hi = 0.f;

    for (int jt = 0; jt < 24; jt++) {
        int j0 = jt * 64;
        int cur = jt & 1;
        float* Kc  = smf + (cur ? OFF_K1 : OFF_K0);
        float* RKc = smf + (cur ? OFF_RK1 : OFF_RK0);
        unsigned mbKcur = cur ? mbK1 : mbK0;
        unsigned mbKnext = cur ? mbK0 : mbK1;

        MBAR_WAIT(mbKcur, (jt >> 1) & 1);
        __syncthreads();

        if (tid == 0) {
            MBAR_EXPECT_TX(mbV, VT_BYTES);
            BULK_G2S(smb + OFF_V * 4, vbaseg + (size_t)j0 * 200, VT_BYTES, mbV);
            if (jt < 23) {
                int mbase = 1472 + (j0 + 64) - q0;
                MBAR_EXPECT_TX(mbKnext, KT_BYTES + RKT_BYTES);
                BULK_G2S(smb + (cur ? OFF_K0 : OFF_K1) * 4,
                         kbaseg + (size_t)(j0 + 64) * 68, KT_BYTES, mbKnext);
                BULK_G2S(smb + (cur ? OFF_RK0 : OFF_RK1) * 4,
                         rkbaseg + (size_t)mbase * 68, RKT_BYTES, mbKnext);
            }
        }

        float acc1[8][4] = {};
        float acc2[4][4] = {};
#pragma unroll
        for (int s = 0; s < 8; s++) {
            int kb = s * 8;
#pragma unroll
            for (int jf = 0; jf < 8; jf++) {
                int cc = nhalf * 64 + jf * 8 + lr;
                unsigned bfr[2];
                bfr[0] = __float_as_uint(RKc[cc * LDK + kb + lc]);
                bfr[1] = __float_as_uint(RKc[cc * LDK + kb + 4 + lc]);
                mma8(acc1[jf], qf[s], bfr);
            }
#pragma unroll
            for (int jf = 0; jf < 4; jf++) {
                int cc = nhalf * 32 + jf * 8 + lr;
                unsigned bfr[2];
                bfr[0] = __float_as_uint(Kc[cc * LDK + kb + lc]);
                bfr[1] = __float_as_uint(Kc[cc * LDK + kb + 4 + lc]);
                mma8(acc2[jf], qf[s], bfr);
            }
        }

        int mbase = 1472 + j0 - q0;
        const float* c2p = c2base + mbase;
#pragma unroll
        for (int jf = 0; jf < 8; jf++) {
            int ml = nhalf * 64 + jf * 8 + 2 * lc;
            float2 c2v = (ml < 127) ? *(const float2*)(c2p + ml) : make_float2(0.f, 0.f);
            *(float2*)&rel[(qw + lr) * LDR + ml] =
                make_float2(acc1[jf][0] + c2v.x, acc1[jf][1] + c2v.y);
            *(float2*)&rel[(qw + 8 + lr) * LDR + ml] =
                make_float2(acc1[jf][2] + c2v.x, acc1[jf][3] + c2v.y);
        }
        __syncthreads();

        const float* c1p = c1base + j0;
        float lg[4][4];
        float mx_lo = -1e30f, mx_hi = -1e30f;
#pragma unroll
        for (int jf = 0; jf < 4; jf++) {
            int jl = nhalf * 32 + jf * 8 + 2 * lc;
            float2 c1v = *(const float2*)(c1p + jl);
            int mlo = 63 + jl - (qw + lr);
            int mhi = mlo - 8;
            lg[jf][0] = acc2[jf][0] + c1v.x + rel[(qw + lr) * LDR + mlo];
            lg[jf][1] = acc2[jf][1] + c1v.y + rel[(qw + lr) * LDR + mlo + 1];
            lg[jf][2] = acc2[jf][2] + c1v.x + rel[(qw + 8 + lr) * LDR + mhi];
            lg[jf][3] = acc2[jf][3] + c1v.y + rel[(qw + 8 + lr) * LDR + mhi + 1];
            mx_lo = fmaxf(mx_lo, fmaxf(lg[jf][0], lg[jf][1]));
            mx_hi = fmaxf(mx_hi, fmaxf(lg[jf][2], lg[jf][3]));
        }
        mx_lo = fmaxf(mx_lo, __shfl_xor_sync(0xffffffffu, mx_lo, 1));
        mx_lo = fmaxf(mx_lo, __shfl_xor_sync(0xffffffffu, mx_lo, 2));
        mx_hi = fmaxf(mx_hi, __shfl_xor_sync(0xffffffffu, mx_hi, 1));
        mx_hi = fmaxf(mx_hi, __shfl_xor_sync(0xffffffffu, mx_hi, 2));
        if (lc == 0) {
            smx[nhalf * 64 + qw + lr] = mx_lo;
            smx[nhalf * 64 + qw + 8 + lr] = mx_hi;
        }
        __syncthreads();
        mx_lo = fmaxf(mx_lo, smx[(1 - nhalf) * 64 + qw + lr]);
        mx_hi = fmaxf(mx_hi, smx[(1 - nhalf) * 64 + qw + 8 + lr]);

        float mn_lo = fmaxf(m_lo, mx_lo), mn_hi = fmaxf(m_hi, mx_hi);
        float sc_lo = __expf(m_lo - mn_lo), sc_hi = __expf(m_hi - mn_hi);
        m_lo = mn_lo; m_hi = mn_hi;
        float su_lo = 0.f, su_hi = 0.f;
        float pv[4][4];
#pragma unroll
        for (int jf = 0; jf < 4; jf++) {
            pv[jf][0] = __expf(lg[jf][0] - mn_lo);
            pv[jf][1] = __expf(lg[jf][1] - mn_lo);
            pv[jf][2] = __expf(lg[jf][2] - mn_hi);
            pv[jf][3] = __expf(lg[jf][3] - mn_hi);
            su_lo += pv[jf][0] + pv[jf][1];
            su_hi += pv[jf][2] + pv[jf][3];
        }
        su_lo += __shfl_xor_sync(0xffffffffu, su_lo, 1);
        su_lo += __shfl_xor_sync(0xffffffffu, su_lo, 2);
        su_hi += __shfl_xor_sync(0xffffffffu, su_hi, 1);
        su_hi += __shfl_xor_sync(0xffffffffu, su_hi, 2);
        if (lc == 0) {
            sms[nhalf * 64 + qw + lr] = su_lo;
            sms[nhalf * 64 + qw + 8 + lr] = su_hi;
        }
#pragma unroll
        for (int jf = 0; jf < 4; jf++) {
            int jl = nhalf * 32 + jf * 8 + 2 * lc;
            *(uint2*)&Ps[(qw + lr) * LDK + jl] =
                make_uint2(f2tf(pv[jf][0]), f2tf(pv[jf][1]));
            *(uint2*)&Ps[(qw + 8 + lr) * LDK + jl] =
                make_uint2(f2tf(pv[jf][2]), f2tf(pv[jf][3]));
        }
        MBAR_WAIT(mbV, jt & 1);
        __syncthreads();
        l_lo = l_lo * sc_lo + su_lo + sms[(1 - nhalf) * 64 + qw + lr];
        l_hi = l_hi * sc_hi + su_hi + sms[(1 - nhalf) * 64 + qw + 8 + lr];

#pragma unroll
        for (int nf = 0; nf < 12; nf++) {
            accO[nf][0] *= sc_lo; accO[nf][1] *= sc_lo;
            accO[nf][2] *= sc_hi; accO[nf][3] *= sc_hi;
        }
#pragma unroll
        for (int s = 0; s < 8; s++) {
            int kb = s * 8;
            unsigned afr[4];
            afr[0] = __float_as_uint(Ps[(qw + lr) * LDK + kb + lc]);
            afr[1] = __float_as_uint(Ps[(qw + 8 + lr) * LDK + kb + lc]);
            afr[2] = __float_as_uint(Ps[(qw + lr) * LDK + kb + 4 + lc]);
            afr[3] = __float_as_uint(Ps[(qw + 8 + lr) * LDK + kb + 4 + lc]);
#pragma unroll
            for (int nf = 0; nf < 12; nf++) {
                int cc = nhalf * 96 + nf * 8 + lr;
                unsigned bfr[2];
                bfr[0] = __float_as_uint(Vs[(kb + lc) * LDV + cc]);
                bfr[1] = __float_as_uint(Vs[(kb + 4 + lc) * LDV + cc]);
                mma8(accO[nf], afr, bfr);
            }
        }
    }

    float il_lo = 1.0f / l_lo, il_hi = 1.0f / l_hi;
    float* og_lo = g_att + (size_t)(b * Tn + q0 + qw + lr) * HV + h * Vn;
    float* og_hi = og_lo + (size_t)8 * HV;
#pragma unroll
    for (int nf = 0; nf < 12; nf++) {
        int cc = nhalf * 96 + nf * 8 + 2 * lc;
        *(float2*)(og_lo + cc) = make_float2(accO[nf][0] * il_lo, accO[nf][1] * il_lo);
        *(float2*)(og_hi + cc) = make_float2(accO[nf][2] * il_hi, accO[nf][3] * il_hi);
    }
}

// ---------------- host orchestration ------------------------------------------
extern "C" void kernel_launch(void* const* d_in, const int* in_sizes, int n_in,
                              void* d_out, int out_size)
{
    (void)in_sizes; (void)n_in; (void)out_size;
    const float* x    = (const float*)d_in[0];
    const float* Wq   = (const float*)d_in[1];
    const float* Wk   = (const float*)d_in[2];
    const float* Wv   = (const float*)d_in[3];
    const float* Wrk  = (const float*)d_in[4];
    const float* Wemb = (const float*)d_in[5];
    const float* rwb  = (const float*)d_in[6];
    const float* rrb  = (const float*)d_in[7];
    float* out = (float*)d_out;

    float *emb, *rkp, *att;
    cudaGetSymbolAddress((void**)&emb, g_emb);
    cudaGetSymbolAddress((void**)&rkp, g_rkp);
    cudaGetSymbolAddress((void**)&att, g_att);

    cudaFuncSetAttribute(flash_kernel, cudaFuncAttributeMaxDynamicSharedMemorySize, SM_BYTES);
    cudaFuncSetAttribute((const void*)tgemm_kernel<3, 64, 68, Rn>,
                         cudaFuncAttributeMaxDynamicSharedMemorySize, GEMM_SMEM);
    cudaFuncSetAttribute((const void*)tgemm_kernel<0, 1, 1, 1>,
                         cudaFuncAttributeMaxDynamicSharedMemorySize, GEMM_SMEM);
    cudaFuncSetAttribute((const void*)qkv_kernel,
                         cudaFuncAttributeMaxDynamicSharedMemorySize, GEMM_SMEM);

    // 1) positional features
    int n1 = Rn * 96;
    pos_fill<<<(n1 + 255) / 256, 256>>>();
    pos_fin<<<(n1 + 255) / 256, 256>>>();

    // 2) r_k = emb @ Wrk -> head-major padded g_rkp
    tgemm_kernel<3, 64, 68, Rn><<<dim3(4, 24), 256, GEMM_SMEM>>>(
        emb, Wrk, rkp, Rn, HK, 192, 192, HK, 0, 1.0f);

    // 3) fused q/k/v projections
    qkv_kernel<<<dim3(20, 24), 256, GEMM_SMEM>>>(x, Wq, Wk, Wv);

    // 4) rank-1 bias terms
    bias2_kernel<<<3072 + Rn, 64>>>(rwb, rrb);

    // 5) fused attention
    flash_kernel<<<dim3(24, 16), 256, SM_BYTES>>>();

    // 6) out = att @ Wemb
    tgemm_kernel<0, 1, 1, 1><<<dim3(12, 24), 256, GEMM_SMEM>>>(
        att, Wemb, out, Bn * Tn, Dn, HV, HV, Dn, Dn, 1.0f);
}

// round 14
// speedup vs baseline: 1.0497x; 1.0497x over previous
#include <cuda_runtime.h>
#include <math.h>

#define Bn 2
#define Tn 1536
#define Dn 1536
#define Hn 8
#define Kn 64
#define Vn 192
#define HK 512
#define HV 1536
#define Rn 3071

// ---------------- scratch ------------------------------------------------------
__device__ float g_emb[(size_t)Rn * 192];
__device__ unsigned g_gmax_bits;
__device__ float g_q[(size_t)Bn * Tn * HK];        // std layout, tf32
__device__ float g_kp[(size_t)Bn * Hn * Tn * 68];  // [(b*8+h)*T+t][68 pitch], tf32
__device__ float g_rkp[(size_t)Hn * Rn * 68];      // [h*3071+m][68 pitch], tf32
__device__ float g_vp[(size_t)Bn * Hn * Tn * 200]; // [(b*8+h)*T+t][200 pitch], tf32
__device__ float g_att[(size_t)Bn * Tn * HV];
__device__ float g_c1[8 * 3072];
__device__ float g_c2[8 * 3072];

// ---------------- helpers ------------------------------------------------------
__device__ __forceinline__ unsigned f2tf(float x) {
    unsigned u; asm("cvt.rna.tf32.f32 %0, %1;" : "=r"(u) : "f"(x)); return u;
}
__device__ __forceinline__ void mma8(float d[4], const unsigned a[4], const unsigned b[2]) {
    asm volatile(
        "mma.sync.aligned.m16n8k8.row.col.f32.tf32.tf32.f32 "
        "{%0,%1,%2,%3}, {%4,%5,%6,%7}, {%8,%9}, {%0,%1,%2,%3};"
        : "+f"(d[0]), "+f"(d[1]), "+f"(d[2]), "+f"(d[3])
        : "r"(a[0]), "r"(a[1]), "r"(a[2]), "r"(a[3]), "r"(b[0]), "r"(b[1]));
}
#define PAIR_BAR(pid) asm volatile("bar.sync %0, 64;" :: "r"(1 + (pid)) : "memory")
#define MBAR_INIT(mb, cnt) \
    asm volatile("mbarrier.init.shared.b64 [%0], %1;" :: "r"(mb), "r"(cnt) : "memory")
#define MBAR_EXPECT_TX(mb, bytes) \
    asm volatile("mbarrier.arrive.expect_tx.shared.b64 _, [%0], %1;" :: "r"(mb), "r"(bytes) : "memory")
#define BULK_G2S(dst, src, bytes, mb) \
    asm volatile("cp.async.bulk.shared::cluster.global.mbarrier::complete_tx::bytes [%0], [%1], %2, [%3];" \
                 :: "r"(dst), "l"(src), "r"(bytes), "r"(mb) : "memory")
#define MBAR_WAIT(mb, parity) do {                                            \
    unsigned _mb = (mb); unsigned _ph = (parity); unsigned _done;             \
    asm volatile("{\n\t.reg .pred p;\n\t"                                     \
        "mbarrier.try_wait.parity.acquire.cta.shared::cta.b64 p, [%1], %2;\n\t" \
        "selp.b32 %0, 1, 0, p;\n\t}"                                          \
        : "=r"(_done) : "r"(_mb), "r"(_ph) : "memory");                       \
    if (!_done) {                                                             \
        asm volatile("{\n\t.reg .pred P1;\n\t"                                \
            "WL_%=:\n\t"                                                      \
            "mbarrier.try_wait.parity.acquire.cta.shared::cta.b64 P1, [%0], %1, 0x989680;\n\t" \
            "@P1 bra.uni WD_%=;\n\t"                                          \
            "bra.uni WL_%=;\n\t"                                              \
            "WD_%=:\n\t}" :: "r"(_mb), "r"(_ph) : "memory");                  \
    }                                                                         \
} while (0)

// ---------------- positional features ------------------------------------------
__global__ void pos_fill() {
    int idx = blockIdx.x * 256 + threadIdx.x;
    bool ok = idx < Rn * 96;
    int p = 0, c = 0;
    float v = 0.f;
    if (ok) {
        p = idx / 96; c = idx % 96;
        float ap = fabsf((float)(p - (Tn - 1)));
        if (c < 32) {
            float max_range = log2f((float)Tn);
            float hl = exp2f(3.0f + (float)c * (max_range - 3.0f) / 31.0f);
            v = exp2f(-ap / hl);
        } else if (c < 64) {
            float w = exp2f((float)(c - 32 + 1)) - 1.0f;
            v = (w > ap) ? 1.0f : 0.0f;
        } else {
            int i = c - 64;
            float mean = 48.0f * (float)(i + 1);
            float conc = (mean / 24.0f) * (mean / 24.0f);
            float rate = mean * (1.0f / 576.0f);
            float lp = (conc - 1.0f) * logf(ap) - rate * ap
                       - (lgammaf(conc) - conc * logf(rate));
            v = expf(lp) + 1e-8f;
        }
        g_emb[(size_t)p * 192 + c] = v;
    }
    float vg = (ok && c >= 64) ? v : 0.f;
#pragma unroll
    for (int o = 16; o > 0; o >>= 1)
        vg = fmaxf(vg, __shfl_xor_sync(0xffffffffu, vg, o));
    if ((threadIdx.x & 31) == 0)
        atomicMax(&g_gmax_bits, __float_as_uint(vg));
}

__global__ void pos_fin() {
    int idx = blockIdx.x * 256 + threadIdx.x;
    if (idx >= Rn * 96) return;
    int p = idx / 96, c = idx % 96;
    float v = g_emb[(size_t)p * 192 + c];
    if (c >= 64) {
        v = v / __uint_as_float(g_gmax_bits);
        g_emb[(size_t)p * 192 + c] = v;
    }
    float sgn = (p < Tn - 1) ? -1.0f : ((p > Tn - 1) ? 1.0f : 0.0f);
    g_emb[(size_t)p * 192 + 96 + c] = sgn * v;
}

// ---------------- rank-1 bias precompute ----------------------------------------
__global__ __launch_bounds__(64) void bias2_kernel(
    const float* __restrict__ rwb, const float* __restrict__ rrb)
{
    int idx = blockIdx.x;
    int t = threadIdx.x;
    int h = t >> 3, part = t & 7;
    const float* sp;
    const float* bp;
    if (idx < 3072) {
        int b = idx >= Tn;
        int tt = idx - (b ? Tn : 0);
        sp = g_kp + ((size_t)(b * 8 + h) * Tn + tt) * 68 + part * 8;
        bp = rwb + h * 64 + part * 8;
    } else {
        int m = idx - 3072;
        sp = g_rkp + ((size_t)h * Rn + m) * 68 + part * 8;
        bp = rrb + h * 64 + part * 8;
    }
    float s = 0.f;
#pragma unroll
    for (int i = 0; i < 8; i++) s = fmaf(bp[i], sp[i], s);
    s += __shfl_down_sync(0xffffffffu, s, 4, 8);
    s += __shfl_down_sync(0xffffffffu, s, 2, 8);
    s += __shfl_down_sync(0xffffffffu, s, 1, 8);
    if (part == 0) {
        if (idx < 3072) g_c1[h * 3072 + idx] = s;
        else            g_c2[h * 3072 + (idx - 3072)] = s;
    }
}

// ---------------- tf32 GEMM body (R10 single-buffer champion) -------------------
template <int SMODE, int HMW, int HMPITCH, int HMT>
__device__ __forceinline__ void gemm_body(
    const float* __restrict__ A, const float* __restrict__ B, float* __restrict__ C,
    int M, int N, int Kd, int lda, int ldb, int ldc,
    int bx, int by, float alpha, unsigned* As, unsigned* Bs)
{
    int tid = threadIdx.x;
    int bm = by * 128, bn = bx * 128;
    int w = tid >> 5, lane = tid & 31;
    int wm = w & 1, wn = w >> 1;
    int lr = lane >> 2, lc = lane & 3;

    int arow0 = tid >> 3;
    int ac4   = (tid & 7) << 2;
    int bc4   = lane << 2;
    bool bvalid = (bn + bc4) < N;
    bool avalid[4];
#pragma unroll
    for (int it = 0; it < 4; it++) avalid[it] = (bm + arow0 + it * 32) < M;

    float4 av[4], bv[4];
    const float4 z4 = make_float4(0.f, 0.f, 0.f, 0.f);
#pragma unroll
    for (int it = 0; it < 4; it++) {
        av[it] = avalid[it] ? *(const float4*)(A + (size_t)(bm + arow0 + it * 32) * lda + ac4) : z4;
        bv[it] = bvalid ? *(const float4*)(B + (size_t)(it * 8 + w) * ldb + bn + bc4) : z4;
    }

    float acc[4][4][4] = {};

    for (int k0 = 0; k0 < Kd; k0 += 32) {
#pragma unroll
        for (int it = 0; it < 4; it++) {
            unsigned* ap = As + (arow0 + it * 32) * 36 + ac4;
            ap[0] = f2tf(av[it].x); ap[1] = f2tf(av[it].y);
            ap[2] = f2tf(av[it].z); ap[3] = f2tf(av[it].w);
            unsigned* bp = Bs + (it * 8 + w) * 136 + bc4;
            bp[0] = f2tf(bv[it].x); bp[1] = f2tf(bv[it].y);
            bp[2] = f2tf(bv[it].z); bp[3] = f2tf(bv[it].w);
        }
        __syncthreads();
        if (k0 + 32 < Kd) {
#pragma unroll
            for (int it = 0; it < 4; it++) {
                av[it] = avalid[it] ? *(const float4*)(A + (size_t)(bm + arow0 + it * 32) * lda + (k0 + 32) + ac4) : z4;
                bv[it] = bvalid ? *(const float4*)(B + (size_t)(k0 + 32 + it * 8 + w) * ldb + bn + bc4) : z4;
            }
        }
#pragma unroll
        for (int s = 0; s < 4; s++) {
            int kb = s * 8;
            unsigned afr[4][4];
#pragma unroll
            for (int i = 0; i < 4; i++) {
                int r = wm * 64 + i * 16 + lr;
                afr[i][0] = As[r * 36 + kb + lc];
                afr[i][1] = As[(r + 8) * 36 + kb + lc];
                afr[i][2] = As[r * 36 + kb + 4 + lc];
                afr[i][3] = As[(r + 8) * 36 + kb + 4 + lc];
            }
            unsigned bfr[4][2];
#pragma unroll
            for (int j = 0; j < 4; j++) {
                int cc = wn * 32 + j * 8 + lr;
                bfr[j][0] = Bs[(kb + lc) * 136 + cc];
                bfr[j][1] = Bs[(kb + 4 + lc) * 136 + cc];
            }
#pragma unroll
            for (int i = 0; i < 4; i++)
#pragma unroll
                for (int j = 0; j < 4; j++)
                    mma8(acc[i][j], afr[i], bfr[j]);
        }
        __syncthreads();
    }

#pragma unroll
    for (int i = 0; i < 4; i++) {
        int r0 = bm + wm * 64 + i * 16 + lr;
#pragma unroll
        for (int j = 0; j < 4; j++) {
            int c0 = bn + wn * 32 + j * 8 + lc * 2;
            if (c0 >= N) continue;
#pragma unroll
            for (int half = 0; half < 2; half++) {
                int r = r0 + half * 8;
                if (r >= M) continue;
                float o0 = alpha * acc[i][j][half * 2];
                float o1 = alpha * acc[i][j][half * 2 + 1];
                if (SMODE != 0) {
                    o0 = __uint_as_float(f2tf(o0));
                    o1 = __uint_as_float(f2tf(o1));
                }
                if (SMODE == 0 || SMODE == 2) {
                    *(float2*)(C + (size_t)r * ldc + c0) = make_float2(o0, o1);
                } else {
                    int bb = r / HMT, tt = r % HMT;
                    int hh = c0 / HMW, cc = c0 % HMW;
                    float* p = C + ((size_t)(bb * Hn + hh) * HMT + tt) * HMPITCH + cc;
                    *(float2*)p = make_float2(o0, o1);
                }
            }
        }
    }
}

template <int SMODE, int HMW, int HMPITCH, int HMT>
__global__ __launch_bounds__(256) void tgemm_kernel(
    const float* __restrict__ A, const float* __restrict__ B, float* __restrict__ C,
    int M, int N, int Kd, int lda, int ldb, int ldc, float alpha)
{
    __shared__ unsigned As[128 * 36];
    __shared__ unsigned Bs[32 * 136];
    gemm_body<SMODE, HMW, HMPITCH, HMT>(A, B, C, M, N, Kd, lda, ldb, ldc,
                                        blockIdx.x, blockIdx.y, alpha, As, Bs);
}

__global__ __launch_bounds__(256) void qkv_kernel(
    const float* __restrict__ x, const float* __restrict__ Wq,
    const float* __restrict__ Wk, const float* __restrict__ Wv)
{
    __shared__ unsigned As[128 * 36];
    __shared__ unsigned Bs[32 * 136];
    int bx = blockIdx.x;
    if (bx < 4) {
        gemm_body<2, 1, 1, 1>(x, Wq, g_q, Bn * Tn, HK, Dn, Dn, HK, HK,
                              bx, blockIdx.y, 0.125f, As, Bs);
    } else if (bx < 8) {
        gemm_body<3, 64, 68, Tn>(x, Wk, g_kp, Bn * Tn, HK, Dn, Dn, HK, 0,
                                 bx - 4, blockIdx.y, 1.0f, As, Bs);
    } else {
        gemm_body<3, 192, 200, Tn>(x, Wv, g_vp, Bn * Tn, HV, Dn, Dn, HV, 0,
                                   bx - 8, blockIdx.y, 1.0f, As, Bs);
    }
}

// ---------------- fused flash attention, bulk-async tiles, pair barriers -------
#define LDK 68
#define LDV 200
#define LDR 132
#define OFF_K0  0
#define OFF_K1  4352
#define OFF_RK0 8704
#define OFF_RK1 17408
#define OFF_V   26112
#define OFF_REL 38912
#define OFF_PS  47360
#define OFF_RED 51712
#define MBAR_BYTE (51968 * 4)
#define SM_BYTES (51968 * 4 + 32)

#define KT_BYTES  (64 * 68 * 4)
#define RKT_BYTES (127 * 68 * 4)
#define VT_BYTES  (64 * 200 * 4)

__global__ __launch_bounds__(256, 1) void flash_kernel() {
    extern __shared__ float smf[];
    float* Vs  = smf + OFF_V;
    float* rel = smf + OFF_REL;
    float* Ps  = smf + OFF_PS;
    float* smx = smf + OFF_RED;
    float* sms = smx + 128;

    unsigned smb = (unsigned)__cvta_generic_to_shared(smf);
    unsigned mbK0 = smb + MBAR_BYTE, mbK1 = smb + MBAR_BYTE + 8, mbV = smb + MBAR_BYTE + 16;

    int bh = blockIdx.y, b = bh >> 3, h = bh & 7;
    int q0 = blockIdx.x * 64;
    int tid = threadIdx.x, w = tid >> 5, lane = tid & 31;
    int lr = lane >> 2, lc = lane & 3;
    int qw = (w >> 1) * 16;
    int nhalf = w & 1;
    int pid = w >> 1;                  // warp-pair id (0..3)

    const float* kbaseg  = g_kp  + (size_t)(b * 8 + h) * Tn * 68;
    const float* rkbaseg = g_rkp + (size_t)h * Rn * 68;
    const float* vbaseg  = g_vp  + (size_t)(b * 8 + h) * Tn * 200;

    if (tid == 0) {
        MBAR_INIT(mbK0, 1);
        MBAR_INIT(mbK1, 1);
        MBAR_INIT(mbV, 1);
    }
    if (tid < 68)  smf[OFF_RK0 + 127 * LDK + tid] = 0.f;
    if (tid >= 68 && tid < 136) smf[OFF_RK1 + 127 * LDK + tid - 68] = 0.f;
    __syncthreads();

    if (tid == 0) {
        int mbase = 1472 - q0;
        MBAR_EXPECT_TX(mbK0, KT_BYTES + RKT_BYTES);
        BULK_G2S(smb + OFF_K0 * 4,  kbaseg, KT_BYTES, mbK0);
        BULK_G2S(smb + OFF_RK0 * 4, rkbaseg + (size_t)mbase * 68, RKT_BYTES, mbK0);
    }

    const float* qg = g_q + (size_t)(b * Tn + q0) * HK + h * Kn;
    unsigned qf[8][4];
#pragma unroll
    for (int s = 0; s < 8; s++) {
        int c = s * 8 + lc;
        qf[s][0] = __float_as_uint(qg[(size_t)(qw + lr) * HK + c]);
        qf[s][1] = __float_as_uint(qg[(size_t)(qw + 8 + lr) * HK + c]);
        qf[s][2] = __float_as_uint(qg[(size_t)(qw + lr) * HK + c + 4]);
        qf[s][3] = __float_as_uint(qg[(size_t)(qw + 8 + lr) * HK + c + 4]);
    }

    const float* c1base = g_c1 + h * 3072 + b * Tn;
    const float* c2base = g_c2 + h * 3072;

    float accO[12][4] = {};
    float m_lo = -1e30f, m_hi = -1e30f, l_lo = 0.f, l_hi = 0.f;

    for (int jt = 0; jt < 24; jt++) {
        int j0 = jt * 64;
        int cur = jt & 1;
        float* Kc  = smf + (cur ? OFF_K1 : OFF_K0);
        float* RKc = smf + (cur ? OFF_RK1 : OFF_RK0);
        unsigned mbKcur = cur ? mbK1 : mbK0;
        unsigned mbKnext = cur ? mbK0 : mbK1;

        MBAR_WAIT(mbKcur, (jt >> 1) & 1);
        __syncthreads();   // FULL: all pairs done reading Vs/rel/Ps of iter t-1

        if (tid == 0) {
            MBAR_EXPECT_TX(mbV, VT_BYTES);
            BULK_G2S(smb + OFF_V * 4, vbaseg + (size_t)j0 * 200, VT_BYTES, mbV);
            if (jt < 23) {
                int mbase = 1472 + (j0 + 64) - q0;
                MBAR_EXPECT_TX(mbKnext, KT_BYTES + RKT_BYTES);
                BULK_G2S(smb + (cur ? OFF_K0 : OFF_K1) * 4,
                         kbaseg + (size_t)(j0 + 64) * 68, KT_BYTES, mbKnext);
                BULK_G2S(smb + (cur ? OFF_RK0 : OFF_RK1) * 4,
                         rkbaseg + (size_t)mbase * 68, RKT_BYTES, mbKnext);
            }
        }

        float acc1[8][4] = {};
        float acc2[4][4] = {};
#pragma unroll
        for (int s = 0; s < 8; s++) {
            int kb = s * 8;
#pragma unroll
            for (int jf = 0; jf < 8; jf++) {
                int cc = nhalf * 64 + jf * 8 + lr;
                unsigned bfr[2];
                bfr[0] = __float_as_uint(RKc[cc * LDK + kb + lc]);
                bfr[1] = __float_as_uint(RKc[cc * LDK + kb + 4 + lc]);
                mma8(acc1[jf], qf[s], bfr);
            }
#pragma unroll
            for (int jf = 0; jf < 4; jf++) {
                int cc = nhalf * 32 + jf * 8 + lr;
                unsigned bfr[2];
                bfr[0] = __float_as_uint(Kc[cc * LDK + kb + lc]);
                bfr[1] = __float_as_uint(Kc[cc * LDK + kb + 4 + lc]);
                mma8(acc2[jf], qf[s], bfr);
            }
        }

        int mbase = 1472 + j0 - q0;
        const float* c2p = c2base + mbase;
#pragma unroll
        for (int jf = 0; jf < 8; jf++) {
            int ml = nhalf * 64 + jf * 8 + 2 * lc;
            float2 c2v = (ml < 127) ? *(const float2*)(c2p + ml) : make_float2(0.f, 0.f);
            *(float2*)&rel[(qw + lr) * LDR + ml] =
                make_float2(acc1[jf][0] + c2v.x, acc1[jf][1] + c2v.y);
            *(float2*)&rel[(qw + 8 + lr) * LDR + ml] =
                make_float2(acc1[jf][2] + c2v.x, acc1[jf][3] + c2v.y);
        }
        PAIR_BAR(pid);     // rel rows of this q-group complete (pair-local)

        const float* c1p = c1base + j0;
        float lg[4][4];
        float mx_lo = -1e30f, mx_hi = -1e30f;
#pragma unroll
        for (int jf = 0; jf < 4; jf++) {
            int jl = nhalf * 32 + jf * 8 + 2 * lc;
            float2 c1v = *(const float2*)(c1p + jl);
            int mlo = 63 + jl - (qw + lr);
            int mhi = mlo - 8;
            lg[jf][0] = acc2[jf][0] + c1v.x + rel[(qw + lr) * LDR + mlo];
            lg[jf][1] = acc2[jf][1] + c1v.y + rel[(qw + lr) * LDR + mlo + 1];
            lg[jf][2] = acc2[jf][2] + c1v.x + rel[(qw + 8 + lr) * LDR + mhi];
            lg[jf][3] = acc2[jf][3] + c1v.y + rel[(qw + 8 + lr) * LDR + mhi + 1];
            mx_lo = fmaxf(mx_lo, fmaxf(lg[jf][0], lg[jf][1]));
            mx_hi = fmaxf(mx_hi, fmaxf(lg[jf][2], lg[jf][3]));
        }
        mx_lo = fmaxf(mx_lo, __shfl_xor_sync(0xffffffffu, mx_lo, 1));
        mx_lo = fmaxf(mx_lo, __shfl_xor_sync(0xffffffffu, mx_lo, 2));
        mx_hi = fmaxf(mx_hi, __shfl_xor_sync(0xffffffffu, mx_hi, 1));
        mx_hi = fmaxf(mx_hi, __shfl_xor_sync(0xffffffffu, mx_hi, 2));
        if (lc == 0) {
            smx[nhalf * 64 + qw + lr] = mx_lo;
            smx[nhalf * 64 + qw + 8 + lr] = mx_hi;
        }
        PAIR_BAR(pid);     // smx exchange within pair
        mx_lo = fmaxf(mx_lo, smx[(1 - nhalf) * 64 + qw + lr]);
        mx_hi = fmaxf(mx_hi, smx[(1 - nhalf) * 64 + qw + 8 + lr]);

        float mn_lo = fmaxf(m_lo, mx_lo), mn_hi = fmaxf(m_hi, mx_hi);
        float sc_lo = __expf(m_lo - mn_lo), sc_hi = __expf(m_hi - mn_hi);
        m_lo = mn_lo; m_hi = mn_hi;
        float su_lo = 0.f, su_hi = 0.f;
        float pv[4][4];
#pragma unroll
        for (int jf = 0; jf < 4; jf++) {
            pv[jf][0] = __expf(lg[jf][0] - mn_lo);
            pv[jf][1] = __expf(lg[jf][1] - mn_lo);
            pv[jf][2] = __expf(lg[jf][2] - mn_hi);
            pv[jf][3] = __expf(lg[jf][3] - mn_hi);
            su_lo += pv[jf][0] + pv[jf][1];
            su_hi += pv[jf][2] + pv[jf][3];
        }
        su_lo += __shfl_xor_sync(0xffffffffu, su_lo, 1);
        su_lo += __shfl_xor_sync(0xffffffffu, su_lo, 2);
        su_hi += __shfl_xor_sync(0xffffffffu, su_hi, 1);
        su_hi += __shfl_xor_sync(0xffffffffu, su_hi, 2);
        if (lc == 0) {
            sms[nhalf * 64 + qw + lr] = su_lo;
            sms[nhalf * 64 + qw + 8 + lr] = su_hi;
        }
#pragma unroll
        for (int jf = 0; jf < 4; jf++) {
            int jl = nhalf * 32 + jf * 8 + 2 * lc;
            *(uint2*)&Ps[(qw + lr) * LDK + jl] =
                make_uint2(f2tf(pv[jf][0]), f2tf(pv[jf][1]));
            *(uint2*)&Ps[(qw + 8 + lr) * LDK + jl] =
                make_uint2(f2tf(pv[jf][2]), f2tf(pv[jf][3]));
        }
        MBAR_WAIT(mbV, jt & 1);
        PAIR_BAR(pid);     // Ps rows + sms exchange within pair; V landed per-thread
        l_lo = l_lo * sc_lo + su_lo + sms[(1 - nhalf) * 64 + qw + lr];
        l_hi = l_hi * sc_hi + su_hi + sms[(1 - nhalf) * 64 + qw + 8 + lr];

#pragma unroll
        for (int nf = 0; nf < 12; nf++) {
            accO[nf][0] *= sc_lo; accO[nf][1] *= sc_lo;
            accO[nf][2] *= sc_hi; accO[nf][3] *= sc_hi;
        }
#pragma unroll
        for (int s = 0; s < 8; s++) {
            int kb = s * 8;
            unsigned afr[4];
            afr[0] = __float_as_uint(Ps[(qw + lr) * LDK + kb + lc]);
            afr[1] = __float_as_uint(Ps[(qw + 8 + lr) * LDK + kb + lc]);
            afr[2] = __float_as_uint(Ps[(qw + lr) * LDK + kb + 4 + lc]);
            afr[3] = __float_as_uint(Ps[(qw + 8 + lr) * LDK + kb + 4 + lc]);
#pragma unroll
            for (int nf = 0; nf < 12; nf++) {
                int cc = nhalf * 96 + nf * 8 + lr;
                unsigned bfr[2];
                bfr[0] = __float_as_uint(Vs[(kb + lc) * LDV + cc]);
                bfr[1] = __float_as_uint(Vs[(kb + 4 + lc) * LDV + cc]);
                mma8(accO[nf], afr, bfr);
            }
        }
    }

    float il_lo = 1.0f / l_lo, il_hi = 1.0f / l_hi;
    float* og_lo = g_att + (size_t)(b * Tn + q0 + qw + lr) * HV + h * Vn;
    float* og_hi = og_lo + (size_t)8 * HV;
#pragma unroll
    for (int nf = 0; nf < 12; nf++) {
        int cc = nhalf * 96 + nf * 8 + 2 * lc;
        *(float2*)(og_lo + cc) = make_float2(accO[nf][0] * il_lo, accO[nf][1] * il_lo);
        *(float2*)(og_hi + cc) = make_float2(accO[nf][2] * il_hi, accO[nf][3] * il_hi);
    }
}

// ---------------- host orchestration ------------------------------------------
extern "C" void kernel_launch(void* const* d_in, const int* in_sizes, int n_in,
                              void* d_out, int out_size)
{
    (void)in_sizes; (void)n_in; (void)out_size;
    const float* x    = (const float*)d_in[0];
    const float* Wq   = (const float*)d_in[1];
    const float* Wk   = (const float*)d_in[2];
    const float* Wv   = (const float*)d_in[3];
    const float* Wrk  = (const float*)d_in[4];
    const float* Wemb = (const float*)d_in[5];
    const float* rwb  = (const float*)d_in[6];
    const float* rrb  = (const float*)d_in[7];
    float* out = (float*)d_out;

    float *emb, *rkp, *att;
    cudaGetSymbolAddress((void**)&emb, g_emb);
    cudaGetSymbolAddress((void**)&rkp, g_rkp);
    cudaGetSymbolAddress((void**)&att, g_att);

    cudaFuncSetAttribute(flash_kernel, cudaFuncAttributeMaxDynamicSharedMemorySize, SM_BYTES);

    // 1) positional features
    int n1 = Rn * 96;
    pos_fill<<<(n1 + 255) / 256, 256>>>();
    pos_fin<<<(n1 + 255) / 256, 256>>>();

    // 2) r_k = emb @ Wrk -> head-major padded g_rkp
    tgemm_kernel<3, 64, 68, Rn><<<dim3(4, 24), 256>>>(
        emb, Wrk, rkp, Rn, HK, 192, 192, HK, 0, 1.0f);

    // 3) fused q/k/v projections
    qkv_kernel<<<dim3(20, 24), 256>>>(x, Wq, Wk, Wv);

    // 4) rank-1 bias terms
    bias2_kernel<<<3072 + Rn, 64>>>(rwb, rrb);

    // 5) fused attention (pair-barrier version)
    flash_kernel<<<dim3(24, 16), 256, SM_BYTES>>>();

    // 6) out = att @ Wemb
    tgemm_kernel<0, 1, 1, 1><<<dim3(12, 24), 256>>>(
        att, Wemb, out, Bn * Tn, Dn, HV, HV, Dn, Dn, 1.0f);
}

// round 16
// speedup vs baseline: 1.1021x; 1.0499x over previous
#include <cuda_runtime.h>
#include <math.h>

#define Bn 2
#define Tn 1536
#define Dn 1536
#define Hn 8
#define Kn 64
#define Vn 192
#define HK 512
#define HV 1536
#define Rn 3071

// ---------------- scratch ------------------------------------------------------
__device__ float g_emb[(size_t)Rn * 192];
__device__ unsigned g_gmax_bits;
__device__ float g_q[(size_t)Bn * Tn * HK];        // std layout, tf32
__device__ float g_kp[(size_t)Bn * Hn * Tn * 68];  // [(b*8+h)*T+t][68 pitch], tf32
__device__ float g_rkp[(size_t)Hn * Rn * 68];      // [h*3071+m][68 pitch], tf32
__device__ float g_vp[(size_t)Bn * Hn * Tn * 200]; // [(b*8+h)*T+t][200 pitch], tf32
__device__ float g_att[(size_t)Bn * Tn * HV];
__device__ float g_c1[8 * 3072];
__device__ float g_c2[8 * 3072];

// ---------------- helpers ------------------------------------------------------
__device__ __forceinline__ unsigned f2tf(float x) {
    unsigned u; asm("cvt.rna.tf32.f32 %0, %1;" : "=r"(u) : "f"(x)); return u;
}
__device__ __forceinline__ void mma8(float d[4], const unsigned a[4], const unsigned b[2]) {
    asm volatile(
        "mma.sync.aligned.m16n8k8.row.col.f32.tf32.tf32.f32 "
        "{%0,%1,%2,%3}, {%4,%5,%6,%7}, {%8,%9}, {%0,%1,%2,%3};"
        : "+f"(d[0]), "+f"(d[1]), "+f"(d[2]), "+f"(d[3])
        : "r"(a[0]), "r"(a[1]), "r"(a[2]), "r"(a[3]), "r"(b[0]), "r"(b[1]));
}
#define PAIR_BAR(pid) asm volatile("bar.sync %0, 64;" :: "r"(1 + (pid)) : "memory")
#define MBAR_INIT(mb, cnt) \
    asm volatile("mbarrier.init.shared.b64 [%0], %1;" :: "r"(mb), "r"(cnt) : "memory")
#define MBAR_EXPECT_TX(mb, bytes) \
    asm volatile("mbarrier.arrive.expect_tx.shared.b64 _, [%0], %1;" :: "r"(mb), "r"(bytes) : "memory")
#define BULK_G2S(dst, src, bytes, mb) \
    asm volatile("cp.async.bulk.shared::cluster.global.mbarrier::complete_tx::bytes [%0], [%1], %2, [%3];" \
                 :: "r"(dst), "l"(src), "r"(bytes), "r"(mb) : "memory")
#define MBAR_WAIT(mb, parity) do {                                            \
    unsigned _mb = (mb); unsigned _ph = (parity); unsigned _done;             \
    asm volatile("{\n\t.reg .pred p;\n\t"                                     \
        "mbarrier.try_wait.parity.acquire.cta.shared::cta.b64 p, [%1], %2;\n\t" \
        "selp.b32 %0, 1, 0, p;\n\t}"                                          \
        : "=r"(_done) : "r"(_mb), "r"(_ph) : "memory");                       \
    if (!_done) {                                                             \
        asm volatile("{\n\t.reg .pred P1;\n\t"                                \
            "WL_%=:\n\t"                                                      \
            "mbarrier.try_wait.parity.acquire.cta.shared::cta.b64 P1, [%0], %1, 0x989680;\n\t" \
            "@P1 bra.uni WD_%=;\n\t"                                          \
            "bra.uni WL_%=;\n\t"                                              \
            "WD_%=:\n\t}" :: "r"(_mb), "r"(_ph) : "memory");                  \
    }                                                                         \
} while (0)

// ---------------- positional features ------------------------------------------
__global__ void pos_fill() {
    int idx = blockIdx.x * 256 + threadIdx.x;
    bool ok = idx < Rn * 96;
    int p = 0, c = 0;
    float v = 0.f;
    if (ok) {
        p = idx / 96; c = idx % 96;
        float ap = fabsf((float)(p - (Tn - 1)));
        if (c < 32) {
            float max_range = log2f((float)Tn);
            float hl = exp2f(3.0f + (float)c * (max_range - 3.0f) / 31.0f);
            v = exp2f(-ap / hl);
        } else if (c < 64) {
            float w = exp2f((float)(c - 32 + 1)) - 1.0f;
            v = (w > ap) ? 1.0f : 0.0f;
        } else {
            int i = c - 64;
            float mean = 48.0f * (float)(i + 1);
            float conc = (mean / 24.0f) * (mean / 24.0f);
            float rate = mean * (1.0f / 576.0f);
            float lp = (conc - 1.0f) * logf(ap) - rate * ap
                       - (lgammaf(conc) - conc * logf(rate));
            v = expf(lp) + 1e-8f;
        }
        g_emb[(size_t)p * 192 + c] = v;
    }
    float vg = (ok && c >= 64) ? v : 0.f;
#pragma unroll
    for (int o = 16; o > 0; o >>= 1)
        vg = fmaxf(vg, __shfl_xor_sync(0xffffffffu, vg, o));
    if ((threadIdx.x & 31) == 0)
        atomicMax(&g_gmax_bits, __float_as_uint(vg));
}

__global__ void pos_fin() {
    int idx = blockIdx.x * 256 + threadIdx.x;
    if (idx >= Rn * 96) return;
    int p = idx / 96, c = idx % 96;
    float v = g_emb[(size_t)p * 192 + c];
    if (c >= 64) {
        v = v / __uint_as_float(g_gmax_bits);
        g_emb[(size_t)p * 192 + c] = v;
    }
    float sgn = (p < Tn - 1) ? -1.0f : ((p > Tn - 1) ? 1.0f : 0.0f);
    g_emb[(size_t)p * 192 + 96 + c] = sgn * v;
}

// ---------------- rank-1 bias precompute ----------------------------------------
__global__ __launch_bounds__(64) void bias2_kernel(
    const float* __restrict__ rwb, const float* __restrict__ rrb)
{
    int idx = blockIdx.x;
    int t = threadIdx.x;
    int h = t >> 3, part = t & 7;
    const float* sp;
    const float* bp;
    if (idx < 3072) {
        int b = idx >= Tn;
        int tt = idx - (b ? Tn : 0);
        sp = g_kp + ((size_t)(b * 8 + h) * Tn + tt) * 68 + part * 8;
        bp = rwb + h * 64 + part * 8;
    } else {
        int m = idx - 3072;
        sp = g_rkp + ((size_t)h * Rn + m) * 68 + part * 8;
        bp = rrb + h * 64 + part * 8;
    }
    float s = 0.f;
#pragma unroll
    for (int i = 0; i < 8; i++) s = fmaf(bp[i], sp[i], s);
    s += __shfl_down_sync(0xffffffffu, s, 4, 8);
    s += __shfl_down_sync(0xffffffffu, s, 2, 8);
    s += __shfl_down_sync(0xffffffffu, s, 1, 8);
    if (part == 0) {
        if (idx < 3072) g_c1[h * 3072 + idx] = s;
        else            g_c2[h * 3072 + (idx - 3072)] = s;
    }
}

// ---------------- tf32 GEMM body (R10 single-buffer champion) -------------------
template <int SMODE, int HMW, int HMPITCH, int HMT>
__device__ __forceinline__ void gemm_body(
    const float* __restrict__ A, const float* __restrict__ B, float* __restrict__ C,
    int M, int N, int Kd, int lda, int ldb, int ldc,
    int bx, int by, float alpha, unsigned* As, unsigned* Bs)
{
    int tid = threadIdx.x;
    int bm = by * 128, bn = bx * 128;
    int w = tid >> 5, lane = tid & 31;
    int wm = w & 1, wn = w >> 1;
    int lr = lane >> 2, lc = lane & 3;

    int arow0 = tid >> 3;
    int ac4   = (tid & 7) << 2;
    int bc4   = lane << 2;
    bool bvalid = (bn + bc4) < N;
    bool avalid[4];
#pragma unroll
    for (int it = 0; it < 4; it++) avalid[it] = (bm + arow0 + it * 32) < M;

    float4 av[4], bv[4];
    const float4 z4 = make_float4(0.f, 0.f, 0.f, 0.f);
#pragma unroll
    for (int it = 0; it < 4; it++) {
        av[it] = avalid[it] ? *(const float4*)(A + (size_t)(bm + arow0 + it * 32) * lda + ac4) : z4;
        bv[it] = bvalid ? *(const float4*)(B + (size_t)(it * 8 + w) * ldb + bn + bc4) : z4;
    }

    float acc[4][4][4] = {};

    for (int k0 = 0; k0 < Kd; k0 += 32) {
#pragma unroll
        for (int it = 0; it < 4; it++) {
            unsigned* ap = As + (arow0 + it * 32) * 36 + ac4;
            ap[0] = f2tf(av[it].x); ap[1] = f2tf(av[it].y);
            ap[2] = f2tf(av[it].z); ap[3] = f2tf(av[it].w);
            unsigned* bp = Bs + (it * 8 + w) * 136 + bc4;
            bp[0] = f2tf(bv[it].x); bp[1] = f2tf(bv[it].y);
            bp[2] = f2tf(bv[it].z); bp[3] = f2tf(bv[it].w);
        }
        __syncthreads();
        if (k0 + 32 < Kd) {
#pragma unroll
            for (int it = 0; it < 4; it++) {
                av[it] = avalid[it] ? *(const float4*)(A + (size_t)(bm + arow0 + it * 32) * lda + (k0 + 32) + ac4) : z4;
                bv[it] = bvalid ? *(const float4*)(B + (size_t)(k0 + 32 + it * 8 + w) * ldb + bn + bc4) : z4;
            }
        }
#pragma unroll
        for (int s = 0; s < 4; s++) {
            int kb = s * 8;
            unsigned afr[4][4];
#pragma unroll
            for (int i = 0; i < 4; i++) {
                int r = wm * 64 + i * 16 + lr;
                afr[i][0] = As[r * 36 + kb + lc];
                afr[i][1] = As[(r + 8) * 36 + kb + lc];
                afr[i][2] = As[r * 36 + kb + 4 + lc];
                afr[i][3] = As[(r + 8) * 36 + kb + 4 + lc];
            }
            unsigned bfr[4][2];
#pragma unroll
            for (int j = 0; j < 4; j++) {
                int cc = wn * 32 + j * 8 + lr;
                bfr[j][0] = Bs[(kb + lc) * 136 + cc];
                bfr[j][1] = Bs[(kb + 4 + lc) * 136 + cc];
            }
#pragma unroll
            for (int i = 0; i < 4; i++)
#pragma unroll
                for (int j = 0; j < 4; j++)
                    mma8(acc[i][j], afr[i], bfr[j]);
        }
        __syncthreads();
    }

#pragma unroll
    for (int i = 0; i < 4; i++) {
        int r0 = bm + wm * 64 + i * 16 + lr;
#pragma unroll
        for (int j = 0; j < 4; j++) {
            int c0 = bn + wn * 32 + j * 8 + lc * 2;
            if (c0 >= N) continue;
#pragma unroll
            for (int half = 0; half < 2; half++) {
                int r = r0 + half * 8;
                if (r >= M) continue;
                float o0 = alpha * acc[i][j][half * 2];
                float o1 = alpha * acc[i][j][half * 2 + 1];
                if (SMODE != 0) {
                    o0 = __uint_as_float(f2tf(o0));
                    o1 = __uint_as_float(f2tf(o1));
                }
                if (SMODE == 0 || SMODE == 2) {
                    *(float2*)(C + (size_t)r * ldc + c0) = make_float2(o0, o1);
                } else {
                    int bb = r / HMT, tt = r % HMT;
                    int hh = c0 / HMW, cc = c0 % HMW;
                    float* p = C + ((size_t)(bb * Hn + hh) * HMT + tt) * HMPITCH + cc;
                    *(float2*)p = make_float2(o0, o1);
                }
            }
        }
    }
}

template <int SMODE, int HMW, int HMPITCH, int HMT>
__global__ __launch_bounds__(256) void tgemm_kernel(
    const float* __restrict__ A, const float* __restrict__ B, float* __restrict__ C,
    int M, int N, int Kd, int lda, int ldb, int ldc, float alpha)
{
    __shared__ unsigned As[128 * 36];
    __shared__ unsigned Bs[32 * 136];
    gemm_body<SMODE, HMW, HMPITCH, HMT>(A, B, C, M, N, Kd, lda, ldb, ldc,
                                        blockIdx.x, blockIdx.y, alpha, As, Bs);
}

__global__ __launch_bounds__(256) void qkv_kernel(
    const float* __restrict__ x, const float* __restrict__ Wq,
    const float* __restrict__ Wk, const float* __restrict__ Wv)
{
    __shared__ unsigned As[128 * 36];
    __shared__ unsigned Bs[32 * 136];
    int bx = blockIdx.x;
    if (bx < 4) {
        gemm_body<2, 1, 1, 1>(x, Wq, g_q, Bn * Tn, HK, Dn, Dn, HK, HK,
                              bx, blockIdx.y, 0.125f, As, Bs);
    } else if (bx < 8) {
        gemm_body<3, 64, 68, Tn>(x, Wk, g_kp, Bn * Tn, HK, Dn, Dn, HK, 0,
                                 bx - 4, blockIdx.y, 1.0f, As, Bs);
    } else {
        gemm_body<3, 192, 200, Tn>(x, Wv, g_vp, Bn * Tn, HV, Dn, Dn, HV, 0,
                                   bx - 8, blockIdx.y, 1.0f, As, Bs);
    }
}

// ---------------- flash attention: rolling-rel, bulk-async, pair barriers ------
#define LDK 68
#define LDV 200
#define LDR 132
#define OFF_K0  0
#define OFF_K1  4352
#define OFF_RK0 8704
#define OFF_RK1 13056
#define OFF_V   17408
#define OFF_REL 30208
#define OFF_PS  38656
#define OFF_RED 43008
#define SM_FLOATS 43264
#define MBAR_BYTE (SM_FLOATS * 4)
#define SM_BYTES (MBAR_BYTE + 32)

#define KT_BYTES  (64 * 68 * 4)
#define VT_BYTES  (64 * 200 * 4)

__global__ __launch_bounds__(256, 1) void flash_kernel() {
    extern __shared__ float smf[];
    float* Vs  = smf + OFF_V;
    float* rel = smf + OFF_REL;     // [64 q][LDR], circular 128 m-slots
    float* Ps  = smf + OFF_PS;
    float* smx = smf + OFF_RED;
    float* sms = smx + 128;

    unsigned smb = (unsigned)__cvta_generic_to_shared(smf);
    unsigned mbK0 = smb + MBAR_BYTE,      mbK1 = smb + MBAR_BYTE + 8;
    unsigned mbV  = smb + MBAR_BYTE + 16, mbP  = smb + MBAR_BYTE + 24;

    int bh = blockIdx.y, b = bh >> 3, h = bh & 7;
    int q0 = blockIdx.x * 64;
    int tid = threadIdx.x, w = tid >> 5, lane = tid & 31;
    int lr = lane >> 2, lc = lane & 3;
    int qw = (w >> 1) * 16;
    int nhalf = w & 1;
    int pid = w >> 1;

    const float* kbaseg  = g_kp  + (size_t)(b * 8 + h) * Tn * 68;
    const float* rkbaseg = g_rkp + (size_t)h * Rn * 68;
    const float* vbaseg  = g_vp  + (size_t)(b * 8 + h) * Tn * 200;

    if (tid == 0) {
        MBAR_INIT(mbK0, 1);
        MBAR_INIT(mbK1, 1);
        MBAR_INIT(mbV, 1);
        MBAR_INIT(mbP, 1);
    }
    __syncthreads();

    int G0 = 1472 - q0;                    // window anchor, slot(m) = (m-G0+1)&127
    if (tid == 0) {
        MBAR_EXPECT_TX(mbP, KT_BYTES);     // prologue RK rows [G0, G0+63] -> RK1
        BULK_G2S(smb + OFF_RK1 * 4, rkbaseg + (size_t)G0 * 68, KT_BYTES, mbP);
        MBAR_EXPECT_TX(mbK0, 2 * KT_BYTES);
        BULK_G2S(smb + OFF_K0 * 4,  kbaseg, KT_BYTES, mbK0);          // K[0]
        BULK_G2S(smb + OFF_RK0 * 4, rkbaseg + (size_t)(G0 + 63) * 68, // RKnew[0]
                 KT_BYTES, mbK0);
    }

    const float* qg = g_q + (size_t)(b * Tn + q0) * HK + h * Kn;
    unsigned qf[8][4];
#pragma unroll
    for (int s = 0; s < 8; s++) {
        int c = s * 8 + lc;
        qf[s][0] = __float_as_uint(qg[(size_t)(qw + lr) * HK + c]);
        qf[s][1] = __float_as_uint(qg[(size_t)(qw + 8 + lr) * HK + c]);
        qf[s][2] = __float_as_uint(qg[(size_t)(qw + lr) * HK + c + 4]);
        qf[s][3] = __float_as_uint(qg[(size_t)(qw + 8 + lr) * HK + c + 4]);
    }

    const float* c1base = g_c1 + h * 3072 + b * Tn;
    const float* c2base = g_c2 + h * 3072;

    // ---- prologue: rel for m in [G0, G0+63] -> slots 1..64 ----
    {
        MBAR_WAIT(mbP, 0);
        float* RKp = smf + OFF_RK1;
        float accp[4][4] = {};
#pragma unroll
        for (int s = 0; s < 8; s++) {
            int kb = s * 8;
#pragma unroll
            for (int jf = 0; jf < 4; jf++) {
                int cc = nhalf * 32 + jf * 8 + lr;
                unsigned bfr[2];
                bfr[0] = __float_as_uint(RKp[cc * LDK + kb + lc]);
                bfr[1] = __float_as_uint(RKp[cc * LDK + kb + 4 + lc]);
                mma8(accp[jf], qf[s], bfr);
            }
        }
#pragma unroll
        for (int jf = 0; jf < 4; jf++) {
            int col = nhalf * 32 + jf * 8 + 2 * lc;
            float c20 = c2base[G0 + col];
            float c21 = c2base[G0 + col + 1];
            rel[(qw + lr) * LDR + col + 1]     = accp[jf][0] + c20;
            rel[(qw + lr) * LDR + col + 2]     = accp[jf][1] + c21;
            rel[(qw + 8 + lr) * LDR + col + 1] = accp[jf][2] + c20;
            rel[(qw + 8 + lr) * LDR + col + 2] = accp[jf][3] + c21;
        }
    }

    float accO[12][4] = {};
    float m_lo = -1e30f, m_hi = -1e30f, l_lo = 0.f, l_hi = 0.f;

    for (int jt = 0; jt < 24; jt++) {
        int j0 = jt * 64;
        int cur = jt & 1;
        float* Kc  = smf + (cur ? OFF_K1 : OFF_K0);
        float* RKc = smf + (cur ? OFF_RK1 : OFF_RK0);
        unsigned mbKcur = cur ? mbK1 : mbK0;
        unsigned mbKnext = cur ? mbK0 : mbK1;

        MBAR_WAIT(mbKcur, (jt >> 1) & 1);
        __syncthreads();   // FULL: orders prev-iter rel/Ps/Vs reads before reuse

        if (tid == 0) {
            MBAR_EXPECT_TX(mbV, VT_BYTES);
            BULK_G2S(smb + OFF_V * 4, vbaseg + (size_t)j0 * 200, VT_BYTES, mbV);
            if (jt < 23) {
                int mstart = G0 + 64 * (jt + 1) + 63;   // new rows for jt+1
                MBAR_EXPECT_TX(mbKnext, 2 * KT_BYTES);
                BULK_G2S(smb + (cur ? OFF_K0 : OFF_K1) * 4,
                         kbaseg + (size_t)(j0 + 64) * 68, KT_BYTES, mbKnext);
                BULK_G2S(smb + (cur ? OFF_RK0 : OFF_RK1) * 4,
                         rkbaseg + (size_t)mstart * 68, KT_BYTES, mbKnext);
            }
        }

        // ---- QK MMAs: rel-new (32 cols/warp) + content (32 cols/warp) ----
        float acc1[4][4] = {};
        float acc2[4][4] = {};
#pragma unroll
        for (int s = 0; s < 8; s++) {
            int kb = s * 8;
#pragma unroll
            for (int jf = 0; jf < 4; jf++) {
                int cc = nhalf * 32 + jf * 8 + lr;
                unsigned bfr[2];
                bfr[0] = __float_as_uint(RKc[cc * LDK + kb + lc]);
                bfr[1] = __float_as_uint(RKc[cc * LDK + kb + 4 + lc]);
                mma8(acc1[jf], qf[s], bfr);
                unsigned bfr2[2];
                bfr2[0] = __float_as_uint(Kc[cc * LDK + kb + lc]);
                bfr2[1] = __float_as_uint(Kc[cc * LDK + kb + 4 + lc]);
                mma8(acc2[jf], qf[s], bfr2);
            }
        }

        // ---- stage rel-new + c2 into circular buffer (even slots, no wrap) ----
        int sbase = (64 * jt + 64) & 127;               // 0 or 64
        const float* c2p = c2base + G0 + 64 * jt + 63;  // ODD base: scalar loads only
#pragma unroll
        for (int jf = 0; jf < 4; jf++) {
            int col = nhalf * 32 + jf * 8 + 2 * lc;
            int slot = sbase + col;                     // <=127, even
            float c20 = c2p[col];
            float c21 = c2p[col + 1];
            *(float2*)&rel[(qw + lr) * LDR + slot] =
                make_float2(acc1[jf][0] + c20, acc1[jf][1] + c21);
            *(float2*)&rel[(qw + 8 + lr) * LDR + slot] =
                make_float2(acc1[jf][2] + c20, acc1[jf][3] + c21);
        }
        PAIR_BAR(pid);     // rel rows of this q-group complete (pair-local)

        // ---- logits = content + c1 + shifted rel; row max ----
        const float* c1p = c1base + j0;
        float lg[4][4];
        float mx_lo = -1e30f, mx_hi = -1e30f;
#pragma unroll
        for (int jf = 0; jf < 4; jf++) {
            int jl = nhalf * 32 + jf * 8 + 2 * lc;
            float2 c1v = *(const float2*)(c1p + jl);
            int d0 = sbase + jl - (qw + lr);            // may be negative
            int d1 = d0 - 8;
            lg[jf][0] = acc2[jf][0] + c1v.x + rel[(qw + lr) * LDR + (d0 & 127)];
            lg[jf][1] = acc2[jf][1] + c1v.y + rel[(qw + lr) * LDR + ((d0 + 1) & 127)];
            lg[jf][2] = acc2[jf][2] + c1v.x + rel[(qw + 8 + lr) * LDR + (d1 & 127)];
            lg[jf][3] = acc2[jf][3] + c1v.y + rel[(qw + 8 + lr) * LDR + ((d1 + 1) & 127)];
            mx_lo = fmaxf(mx_lo, fmaxf(lg[jf][0], lg[jf][1]));
            mx_hi = fmaxf(mx_hi, fmaxf(lg[jf][2], lg[jf][3]));
        }
        mx_lo = fmaxf(mx_lo, __shfl_xor_sync(0xffffffffu, mx_lo, 1));
        mx_lo = fmaxf(mx_lo, __shfl_xor_sync(0xffffffffu, mx_lo, 2));
        mx_hi = fmaxf(mx_hi, __shfl_xor_sync(0xffffffffu, mx_hi, 1));
        mx_hi = fmaxf(mx_hi, __shfl_xor_sync(0xffffffffu, mx_hi, 2));
        if (lc == 0) {
            smx[nhalf * 64 + qw + lr] = mx_lo;
            smx[nhalf * 64 + qw + 8 + lr] = mx_hi;
        }
        PAIR_BAR(pid);
        mx_lo = fmaxf(mx_lo, smx[(1 - nhalf) * 64 + qw + lr]);
        mx_hi = fmaxf(mx_hi, smx[(1 - nhalf) * 64 + qw + 8 + lr]);

        float mn_lo = fmaxf(m_lo, mx_lo), mn_hi = fmaxf(m_hi, mx_hi);
        float sc_lo = __expf(m_lo - mn_lo), sc_hi = __expf(m_hi - mn_hi);
        m_lo = mn_lo; m_hi = mn_hi;
        float su_lo = 0.f, su_hi = 0.f;
        float pv[4][4];
#pragma unroll
        for (int jf = 0; jf < 4; jf++) {
            pv[jf][0] = __expf(lg[jf][0] - mn_lo);
            pv[jf][1] = __expf(lg[jf][1] - mn_lo);
            pv[jf][2] = __expf(lg[jf][2] - mn_hi);
            pv[jf][3] = __expf(lg[jf][3] - mn_hi);
            su_lo += pv[jf][0] + pv[jf][1];
            su_hi += pv[jf][2] + pv[jf][3];
        }
        su_lo += __shfl_xor_sync(0xffffffffu, su_lo, 1);
        su_lo += __shfl_xor_sync(0xffffffffu, su_lo, 2);
        su_hi += __shfl_xor_sync(0xffffffffu, su_hi, 1);
        su_hi += __shfl_xor_sync(0xffffffffu, su_hi, 2);
        if (lc == 0) {
            sms[nhalf * 64 + qw + lr] = su_lo;
            sms[nhalf * 64 + qw + 8 + lr] = su_hi;
        }
#pragma unroll
        for (int jf = 0; jf < 4; jf++) {
            int jl = nhalf * 32 + jf * 8 + 2 * lc;
            *(uint2*)&Ps[(qw + lr) * LDK + jl] =
                make_uint2(f2tf(pv[jf][0]), f2tf(pv[jf][1]));
            *(uint2*)&Ps[(qw + 8 + lr) * LDK + jl] =
                make_uint2(f2tf(pv[jf][2]), f2tf(pv[jf][3]));
        }
        MBAR_WAIT(mbV, jt & 1);
        PAIR_BAR(pid);
        l_lo = l_lo * sc_lo + su_lo + sms[(1 - nhalf) * 64 + qw + lr];
        l_hi = l_hi * sc_hi + su_hi + sms[(1 - nhalf) * 64 + qw + 8 + lr];

#pragma unroll
        for (int nf = 0; nf < 12; nf++) {
            accO[nf][0] *= sc_lo; accO[nf][1] *= sc_lo;
            accO[nf][2] *= sc_hi; accO[nf][3] *= sc_hi;
        }
#pragma unroll
        for (int s = 0; s < 8; s++) {
            int kb = s * 8;
            unsigned afr[4];
            afr[0] = __float_as_uint(Ps[(qw + lr) * LDK + kb + lc]);
            afr[1] = __float_as_uint(Ps[(qw + 8 + lr) * LDK + kb + lc]);
            afr[2] = __float_as_uint(Ps[(qw + lr) * LDK + kb + 4 + lc]);
            afr[3] = __float_as_uint(Ps[(qw + 8 + lr) * LDK + kb + 4 + lc]);
#pragma unroll
            for (int nf = 0; nf < 12; nf++) {
                int cc = nhalf * 96 + nf * 8 + lr;
                unsigned bfr[2];
                bfr[0] = __float_as_uint(Vs[(kb + lc) * LDV + cc]);
                bfr[1] = __float_as_uint(Vs[(kb + 4 + lc) * LDV + cc]);
                mma8(accO[nf], afr, bfr);
            }
        }
    }

    float il_lo = 1.0f / l_lo, il_hi = 1.0f / l_hi;
    float* og_lo = g_att + (size_t)(b * Tn + q0 + qw + lr) * HV + h * Vn;
    float* og_hi = og_lo + (size_t)8 * HV;
#pragma unroll
    for (int nf = 0; nf < 12; nf++) {
        int cc = nhalf * 96 + nf * 8 + 2 * lc;
        *(float2*)(og_lo + cc) = make_float2(accO[nf][0] * il_lo, accO[nf][1] * il_lo);
        *(float2*)(og_hi + cc) = make_float2(accO[nf][2] * il_hi, accO[nf][3] * il_hi);
    }
}

// ---------------- host orchestration ------------------------------------------
extern "C" void kernel_launch(void* const* d_in, const int* in_sizes, int n_in,
                              void* d_out, int out_size)
{
    (void)in_sizes; (void)n_in; (void)out_size;
    const float* x    = (const float*)d_in[0];
    const float* Wq   = (const float*)d_in[1];
    const float* Wk   = (const float*)d_in[2];
    const float* Wv   = (const float*)d_in[3];
    const float* Wrk  = (const float*)d_in[4];
    const float* Wemb = (const float*)d_in[5];
    const float* rwb  = (const float*)d_in[6];
    const float* rrb  = (const float*)d_in[7];
    float* out = (float*)d_out;

    float *emb, *rkp, *att;
    cudaGetSymbolAddress((void**)&emb, g_emb);
    cudaGetSymbolAddress((void**)&rkp, g_rkp);
    cudaGetSymbolAddress((void**)&att, g_att);

    cudaFuncSetAttribute(flash_kernel, cudaFuncAttributeMaxDynamicSharedMemorySize, SM_BYTES);

    // 1) positional features
    int n1 = Rn * 96;
    pos_fill<<<(n1 + 255) / 256, 256>>>();
    pos_fin<<<(n1 + 255) / 256, 256>>>();

    // 2) r_k = emb @ Wrk -> head-major padded g_rkp
    tgemm_kernel<3, 64, 68, Rn><<<dim3(4, 24), 256>>>(
        emb, Wrk, rkp, Rn, HK, 192, 192, HK, 0, 1.0f);

    // 3) fused q/k/v projections
    qkv_kernel<<<dim3(20, 24), 256>>>(x, Wq, Wk, Wv);

    // 4) rank-1 bias terms
    bias2_kernel<<<3072 + Rn, 64>>>(rwb, rrb);

    // 5) fused attention (rolling-rel version)
    flash_kernel<<<dim3(24, 16), 256, SM_BYTES>>>();

    // 6) out = att @ Wemb
    tgemm_kernel<0, 1, 1, 1><<<dim3(12, 24), 256>>>(
        att, Wemb, out, Bn * Tn, Dn, HV, HV, Dn, Dn, 1.0f);
}

// round 17
// speedup vs baseline: 1.1146x; 1.0114x over previous
#include <cuda_runtime.h>
#include <math.h>

#define Bn 2
#define Tn 1536
#define Dn 1536
#define Hn 8
#define Kn 64
#define Vn 192
#define HK 512
#define HV 1536
#define Rn 3071

// ---------------- scratch ------------------------------------------------------
__device__ float g_emb[(size_t)Rn * 192];
__device__ unsigned g_gmax_bits;
__device__ float g_q[(size_t)Bn * Tn * HK];        // std layout, tf32
__device__ float g_kp[(size_t)Bn * Hn * Tn * 68];  // [(b*8+h)*T+t][68 pitch], tf32
__device__ float g_rkp[(size_t)Hn * Rn * 68];      // [h*3071+m][68 pitch], tf32
__device__ float g_vp[(size_t)Bn * Hn * Tn * 200]; // [(b*8+h)*T+t][200 pitch], tf32
__device__ float g_att[(size_t)Bn * Tn * HV];
__device__ float g_c1[8 * 3072];
__device__ float g_c2[8 * 3072];

// ---------------- helpers ------------------------------------------------------
__device__ __forceinline__ unsigned f2tf(float x) {
    unsigned u; asm("cvt.rna.tf32.f32 %0, %1;" : "=r"(u) : "f"(x)); return u;
}
__device__ __forceinline__ void mma8(float d[4], const unsigned a[4], const unsigned b[2]) {
    asm volatile(
        "mma.sync.aligned.m16n8k8.row.col.f32.tf32.tf32.f32 "
        "{%0,%1,%2,%3}, {%4,%5,%6,%7}, {%8,%9}, {%0,%1,%2,%3};"
        : "+f"(d[0]), "+f"(d[1]), "+f"(d[2]), "+f"(d[3])
        : "r"(a[0]), "r"(a[1]), "r"(a[2]), "r"(a[3]), "r"(b[0]), "r"(b[1]));
}
#define PAIR_BAR(pid) asm volatile("bar.sync %0, 64;" :: "r"(1 + (pid)) : "memory")
#define MBAR_INIT(mb, cnt) \
    asm volatile("mbarrier.init.shared.b64 [%0], %1;" :: "r"(mb), "r"(cnt) : "memory")
#define MBAR_EXPECT_TX(mb, bytes) \
    asm volatile("mbarrier.arrive.expect_tx.shared.b64 _, [%0], %1;" :: "r"(mb), "r"(bytes) : "memory")
#define BULK_G2S(dst, src, bytes, mb) \
    asm volatile("cp.async.bulk.shared::cluster.global.mbarrier::complete_tx::bytes [%0], [%1], %2, [%3];" \
                 :: "r"(dst), "l"(src), "r"(bytes), "r"(mb) : "memory")
#define MBAR_WAIT(mb, parity) do {                                            \
    unsigned _mb = (mb); unsigned _ph = (parity); unsigned _done;             \
    asm volatile("{\n\t.reg .pred p;\n\t"                                     \
        "mbarrier.try_wait.parity.acquire.cta.shared::cta.b64 p, [%1], %2;\n\t" \
        "selp.b32 %0, 1, 0, p;\n\t}"                                          \
        : "=r"(_done) : "r"(_mb), "r"(_ph) : "memory");                       \
    if (!_done) {                                                             \
        asm volatile("{\n\t.reg .pred P1;\n\t"                                \
            "WL_%=:\n\t"                                                      \
            "mbarrier.try_wait.parity.acquire.cta.shared::cta.b64 P1, [%0], %1, 0x989680;\n\t" \
            "@P1 bra.uni WD_%=;\n\t"                                          \
            "bra.uni WL_%=;\n\t"                                              \
            "WD_%=:\n\t}" :: "r"(_mb), "r"(_ph) : "memory");                  \
    }                                                                         \
} while (0)

// ---------------- positional features ------------------------------------------
__global__ void pos_fill() {
    int idx = blockIdx.x * 256 + threadIdx.x;
    bool ok = idx < Rn * 96;
    int p = 0, c = 0;
    float v = 0.f;
    if (ok) {
        p = idx / 96; c = idx % 96;
        float ap = fabsf((float)(p - (Tn - 1)));
        if (c < 32) {
            float max_range = log2f((float)Tn);
            float hl = exp2f(3.0f + (float)c * (max_range - 3.0f) / 31.0f);
            v = exp2f(-ap / hl);
        } else if (c < 64) {
            float w = exp2f((float)(c - 32 + 1)) - 1.0f;
            v = (w > ap) ? 1.0f : 0.0f;
        } else {
            int i = c - 64;
            float mean = 48.0f * (float)(i + 1);
            float conc = (mean / 24.0f) * (mean / 24.0f);
            float rate = mean * (1.0f / 576.0f);
            float lp = (conc - 1.0f) * logf(ap) - rate * ap
                       - (lgammaf(conc) - conc * logf(rate));
            v = expf(lp) + 1e-8f;
        }
        g_emb[(size_t)p * 192 + c] = v;
    }
    float vg = (ok && c >= 64) ? v : 0.f;
#pragma unroll
    for (int o = 16; o > 0; o >>= 1)
        vg = fmaxf(vg, __shfl_xor_sync(0xffffffffu, vg, o));
    if ((threadIdx.x & 31) == 0)
        atomicMax(&g_gmax_bits, __float_as_uint(vg));
}

__global__ void pos_fin() {
    int idx = blockIdx.x * 256 + threadIdx.x;
    if (idx >= Rn * 96) return;
    int p = idx / 96, c = idx % 96;
    float v = g_emb[(size_t)p * 192 + c];
    if (c >= 64) {
        v = v / __uint_as_float(g_gmax_bits);
        g_emb[(size_t)p * 192 + c] = v;
    }
    float sgn = (p < Tn - 1) ? -1.0f : ((p > Tn - 1) ? 1.0f : 0.0f);
    g_emb[(size_t)p * 192 + 96 + c] = sgn * v;
}

// ---------------- rank-1 bias precompute ----------------------------------------
__global__ __launch_bounds__(64) void bias2_kernel(
    const float* __restrict__ rwb, const float* __restrict__ rrb)
{
    int idx = blockIdx.x;
    int t = threadIdx.x;
    int h = t >> 3, part = t & 7;
    const float* sp;
    const float* bp;
    if (idx < 3072) {
        int b = idx >= Tn;
        int tt = idx - (b ? Tn : 0);
        sp = g_kp + ((size_t)(b * 8 + h) * Tn + tt) * 68 + part * 8;
        bp = rwb + h * 64 + part * 8;
    } else {
        int m = idx - 3072;
        sp = g_rkp + ((size_t)h * Rn + m) * 68 + part * 8;
        bp = rrb + h * 64 + part * 8;
    }
    float s = 0.f;
#pragma unroll
    for (int i = 0; i < 8; i++) s = fmaf(bp[i], sp[i], s);
    s += __shfl_down_sync(0xffffffffu, s, 4, 8);
    s += __shfl_down_sync(0xffffffffu, s, 2, 8);
    s += __shfl_down_sync(0xffffffffu, s, 1, 8);
    if (part == 0) {
        if (idx < 3072) g_c1[h * 3072 + idx] = s;
        else            g_c2[h * 3072 + (idx - 3072)] = s;
    }
}

// ---------------- tf32 GEMM body (R10 single-buffer champion) -------------------
template <int SMODE, int HMW, int HMPITCH, int HMT>
__device__ __forceinline__ void gemm_body(
    const float* __restrict__ A, const float* __restrict__ B, float* __restrict__ C,
    int M, int N, int Kd, int lda, int ldb, int ldc,
    int bx, int by, float alpha, unsigned* As, unsigned* Bs)
{
    int tid = threadIdx.x;
    int bm = by * 128, bn = bx * 128;
    int w = tid >> 5, lane = tid & 31;
    int wm = w & 1, wn = w >> 1;
    int lr = lane >> 2, lc = lane & 3;

    int arow0 = tid >> 3;
    int ac4   = (tid & 7) << 2;
    int bc4   = lane << 2;
    bool bvalid = (bn + bc4) < N;
    bool avalid[4];
#pragma unroll
    for (int it = 0; it < 4; it++) avalid[it] = (bm + arow0 + it * 32) < M;

    float4 av[4], bv[4];
    const float4 z4 = make_float4(0.f, 0.f, 0.f, 0.f);
#pragma unroll
    for (int it = 0; it < 4; it++) {
        av[it] = avalid[it] ? *(const float4*)(A + (size_t)(bm + arow0 + it * 32) * lda + ac4) : z4;
        bv[it] = bvalid ? *(const float4*)(B + (size_t)(it * 8 + w) * ldb + bn + bc4) : z4;
    }

    float acc[4][4][4] = {};

    for (int k0 = 0; k0 < Kd; k0 += 32) {
#pragma unroll
        for (int it = 0; it < 4; it++) {
            unsigned* ap = As + (arow0 + it * 32) * 36 + ac4;
            ap[0] = f2tf(av[it].x); ap[1] = f2tf(av[it].y);
            ap[2] = f2tf(av[it].z); ap[3] = f2tf(av[it].w);
            unsigned* bp = Bs + (it * 8 + w) * 136 + bc4;
            bp[0] = f2tf(bv[it].x); bp[1] = f2tf(bv[it].y);
            bp[2] = f2tf(bv[it].z); bp[3] = f2tf(bv[it].w);
        }
        __syncthreads();
        if (k0 + 32 < Kd) {
#pragma unroll
            for (int it = 0; it < 4; it++) {
                av[it] = avalid[it] ? *(const float4*)(A + (size_t)(bm + arow0 + it * 32) * lda + (k0 + 32) + ac4) : z4;
                bv[it] = bvalid ? *(const float4*)(B + (size_t)(k0 + 32 + it * 8 + w) * ldb + bn + bc4) : z4;
            }
        }
#pragma unroll
        for (int s = 0; s < 4; s++) {
            int kb = s * 8;
            unsigned afr[4][4];
#pragma unroll
            for (int i = 0; i < 4; i++) {
                int r = wm * 64 + i * 16 + lr;
                afr[i][0] = As[r * 36 + kb + lc];
                afr[i][1] = As[(r + 8) * 36 + kb + lc];
                afr[i][2] = As[r * 36 + kb + 4 + lc];
                afr[i][3] = As[(r + 8) * 36 + kb + 4 + lc];
            }
            unsigned bfr[4][2];
#pragma unroll
            for (int j = 0; j < 4; j++) {
                int cc = wn * 32 + j * 8 + lr;
                bfr[j][0] = Bs[(kb + lc) * 136 + cc];
                bfr[j][1] = Bs[(kb + 4 + lc) * 136 + cc];
            }
#pragma unroll
            for (int i = 0; i < 4; i++)
#pragma unroll
                for (int j = 0; j < 4; j++)
                    mma8(acc[i][j], afr[i], bfr[j]);
        }
        __syncthreads();
    }

#pragma unroll
    for (int i = 0; i < 4; i++) {
        int r0 = bm + wm * 64 + i * 16 + lr;
#pragma unroll
        for (int j = 0; j < 4; j++) {
            int c0 = bn + wn * 32 + j * 8 + lc * 2;
            if (c0 >= N) continue;
#pragma unroll
            for (int half = 0; half < 2; half++) {
                int r = r0 + half * 8;
                if (r >= M) continue;
                float o0 = alpha * acc[i][j][half * 2];
                float o1 = alpha * acc[i][j][half * 2 + 1];
                if (SMODE != 0) {
                    o0 = __uint_as_float(f2tf(o0));
                    o1 = __uint_as_float(f2tf(o1));
                }
                if (SMODE == 0 || SMODE == 2) {
                    *(float2*)(C + (size_t)r * ldc + c0) = make_float2(o0, o1);
                } else {
                    int bb = r / HMT, tt = r % HMT;
                    int hh = c0 / HMW, cc = c0 % HMW;
                    float* p = C + ((size_t)(bb * Hn + hh) * HMT + tt) * HMPITCH + cc;
                    *(float2*)p = make_float2(o0, o1);
                }
            }
        }
    }
}

template <int SMODE, int HMW, int HMPITCH, int HMT>
__global__ __launch_bounds__(256) void tgemm_kernel(
    const float* __restrict__ A, const float* __restrict__ B, float* __restrict__ C,
    int M, int N, int Kd, int lda, int ldb, int ldc, float alpha)
{
    __shared__ unsigned As[128 * 36];
    __shared__ unsigned Bs[32 * 136];
    gemm_body<SMODE, HMW, HMPITCH, HMT>(A, B, C, M, N, Kd, lda, ldb, ldc,
                                        blockIdx.x, blockIdx.y, alpha, As, Bs);
}

__global__ __launch_bounds__(256) void qkv_kernel(
    const float* __restrict__ x, const float* __restrict__ Wq,
    const float* __restrict__ Wk, const float* __restrict__ Wv)
{
    __shared__ unsigned As[128 * 36];
    __shared__ unsigned Bs[32 * 136];
    int bx = blockIdx.x;
    if (bx < 4) {
        gemm_body<2, 1, 1, 1>(x, Wq, g_q, Bn * Tn, HK, Dn, Dn, HK, HK,
                              bx, blockIdx.y, 0.125f, As, Bs);
    } else if (bx < 8) {
        gemm_body<3, 64, 68, Tn>(x, Wk, g_kp, Bn * Tn, HK, Dn, Dn, HK, 0,
                                 bx - 4, blockIdx.y, 1.0f, As, Bs);
    } else {
        gemm_body<3, 192, 200, Tn>(x, Wv, g_vp, Bn * Tn, HV, Dn, Dn, HV, 0,
                                   bx - 8, blockIdx.y, 1.0f, As, Bs);
    }
}

// ---------------- flash: rolling-rel, double-buffered V, pair barriers ---------
#define LDK 68
#define LDV 200
#define LDR 132
#define OFF_K0  0
#define OFF_K1  4352
#define OFF_RK0 8704
#define OFF_RK1 13056
#define OFF_V0  17408
#define OFF_V1  30208
#define OFF_REL 43008
#define OFF_PS  51456
#define OFF_RED 55808
#define SM_FLOATS 56064
#define MBAR_BYTE (SM_FLOATS * 4)
#define SM_BYTES (MBAR_BYTE + 40)

#define KT_BYTES  (64 * 68 * 4)
#define VT_BYTES  (64 * 200 * 4)

__global__ __launch_bounds__(256, 1) void flash_kernel() {
    extern __shared__ float smf[];
    float* rel = smf + OFF_REL;     // [64 q][LDR], circular 128 m-slots
    float* Ps  = smf + OFF_PS;
    float* smx = smf + OFF_RED;
    float* sms = smx + 128;

    unsigned smb = (unsigned)__cvta_generic_to_shared(smf);
    unsigned mbK0 = smb + MBAR_BYTE,      mbK1 = smb + MBAR_BYTE + 8;
    unsigned mbV0 = smb + MBAR_BYTE + 16, mbV1 = smb + MBAR_BYTE + 24;
    unsigned mbP  = smb + MBAR_BYTE + 32;

    int bh = blockIdx.y, b = bh >> 3, h = bh & 7;
    int q0 = blockIdx.x * 64;
    int tid = threadIdx.x, w = tid >> 5, lane = tid & 31;
    int lr = lane >> 2, lc = lane & 3;
    int qw = (w >> 1) * 16;
    int nhalf = w & 1;
    int pid = w >> 1;

    const float* kbaseg  = g_kp  + (size_t)(b * 8 + h) * Tn * 68;
    const float* rkbaseg = g_rkp + (size_t)h * Rn * 68;
    const float* vbaseg  = g_vp  + (size_t)(b * 8 + h) * Tn * 200;

    if (tid == 0) {
        MBAR_INIT(mbK0, 1);
        MBAR_INIT(mbK1, 1);
        MBAR_INIT(mbV0, 1);
        MBAR_INIT(mbV1, 1);
        MBAR_INIT(mbP, 1);
    }
    __syncthreads();

    int G0 = 1472 - q0;                    // window anchor, slot(m) = (m-G0+1)&127
    if (tid == 0) {
        MBAR_EXPECT_TX(mbP, KT_BYTES);     // prologue RK rows [G0, G0+63] -> RK1
        BULK_G2S(smb + OFF_RK1 * 4, rkbaseg + (size_t)G0 * 68, KT_BYTES, mbP);
        MBAR_EXPECT_TX(mbK0, 2 * KT_BYTES);
        BULK_G2S(smb + OFF_K0 * 4,  kbaseg, KT_BYTES, mbK0);          // K[0]
        BULK_G2S(smb + OFF_RK0 * 4, rkbaseg + (size_t)(G0 + 63) * 68, // RKnew[0]
                 KT_BYTES, mbK0);
        MBAR_EXPECT_TX(mbV0, VT_BYTES);                               // V[0]
        BULK_G2S(smb + OFF_V0 * 4, vbaseg, VT_BYTES, mbV0);
    }

    const float* qg = g_q + (size_t)(b * Tn + q0) * HK + h * Kn;
    unsigned qf[8][4];
#pragma unroll
    for (int s = 0; s < 8; s++) {
        int c = s * 8 + lc;
        qf[s][0] = __float_as_uint(qg[(size_t)(qw + lr) * HK + c]);
        qf[s][1] = __float_as_uint(qg[(size_t)(qw + 8 + lr) * HK + c]);
        qf[s][2] = __float_as_uint(qg[(size_t)(qw + lr) * HK + c + 4]);
        qf[s][3] = __float_as_uint(qg[(size_t)(qw + 8 + lr) * HK + c + 4]);
    }

    const float* c1base = g_c1 + h * 3072 + b * Tn;
    const float* c2base = g_c2 + h * 3072;

    // ---- prologue: rel for m in [G0, G0+63] -> slots 1..64 ----
    {
        MBAR_WAIT(mbP, 0);
        float* RKp = smf + OFF_RK1;
        float accp[4][4] = {};
#pragma unroll
        for (int s = 0; s < 8; s++) {
            int kb = s * 8;
#pragma unroll
            for (int jf = 0; jf < 4; jf++) {
                int cc = nhalf * 32 + jf * 8 + lr;
                unsigned bfr[2];
                bfr[0] = __float_as_uint(RKp[cc * LDK + kb + lc]);
                bfr[1] = __float_as_uint(RKp[cc * LDK + kb + 4 + lc]);
                mma8(accp[jf], qf[s], bfr);
            }
        }
#pragma unroll
        for (int jf = 0; jf < 4; jf++) {
            int col = nhalf * 32 + jf * 8 + 2 * lc;
            float c20 = c2base[G0 + col];
            float c21 = c2base[G0 + col + 1];
            rel[(qw + lr) * LDR + col + 1]     = accp[jf][0] + c20;
            rel[(qw + lr) * LDR + col + 2]     = accp[jf][1] + c21;
            rel[(qw + 8 + lr) * LDR + col + 1] = accp[jf][2] + c20;
            rel[(qw + 8 + lr) * LDR + col + 2] = accp[jf][3] + c21;
        }
    }

    float accO[12][4] = {};
    float m_lo = -1e30f, m_hi = -1e30f, l_lo = 0.f, l_hi = 0.f;

    for (int jt = 0; jt < 24; jt++) {
        int j0 = jt * 64;
        int cur = jt & 1;
        float* Kc  = smf + (cur ? OFF_K1 : OFF_K0);
        float* RKc = smf + (cur ? OFF_RK1 : OFF_RK0);
        float* Vs  = smf + (cur ? OFF_V1 : OFF_V0);
        unsigned mbKcur = cur ? mbK1 : mbK0;
        unsigned mbKnext = cur ? mbK0 : mbK1;
        unsigned mbVcur = cur ? mbV1 : mbV0;
        unsigned mbVnext = cur ? mbV0 : mbV1;

        MBAR_WAIT(mbKcur, (jt >> 1) & 1);
        __syncthreads();   // FULL: orders prev-iter rel/Ps/Vs reads before reuse

        if (tid == 0 && jt < 23) {
            int mstart = G0 + 64 * (jt + 1) + 63;   // new rows for jt+1
            MBAR_EXPECT_TX(mbKnext, 2 * KT_BYTES);
            BULK_G2S(smb + (cur ? OFF_K0 : OFF_K1) * 4,
                     kbaseg + (size_t)(j0 + 64) * 68, KT_BYTES, mbKnext);
            BULK_G2S(smb + (cur ? OFF_RK0 : OFF_RK1) * 4,
                     rkbaseg + (size_t)mstart * 68, KT_BYTES, mbKnext);
            MBAR_EXPECT_TX(mbVnext, VT_BYTES);      // V[jt+1]
            BULK_G2S(smb + (cur ? OFF_V0 : OFF_V1) * 4,
                     vbaseg + (size_t)(j0 + 64) * 200, VT_BYTES, mbVnext);
        }

        // ---- QK MMAs: rel-new (32 cols/warp) + content (32 cols/warp) ----
        float acc1[4][4] = {};
        float acc2[4][4] = {};
#pragma unroll
        for (int s = 0; s < 8; s++) {
            int kb = s * 8;
#pragma unroll
            for (int jf = 0; jf < 4; jf++) {
                int cc = nhalf * 32 + jf * 8 + lr;
                unsigned bfr[2];
                bfr[0] = __float_as_uint(RKc[cc * LDK + kb + lc]);
                bfr[1] = __float_as_uint(RKc[cc * LDK + kb + 4 + lc]);
                mma8(acc1[jf], qf[s], bfr);
                unsigned bfr2[2];
                bfr2[0] = __float_as_uint(Kc[cc * LDK + kb + lc]);
                bfr2[1] = __float_as_uint(Kc[cc * LDK + kb + 4 + lc]);
                mma8(acc2[jf], qf[s], bfr2);
            }
        }

        // ---- stage rel-new + c2 into circular buffer (even slots, no wrap) ----
        int sbase = (64 * jt + 64) & 127;               // 0 or 64
        const float* c2p = c2base + G0 + 64 * jt + 63;  // ODD base: scalar loads only
#pragma unroll
        for (int jf = 0; jf < 4; jf++) {
            int col = nhalf * 32 + jf * 8 + 2 * lc;
            int slot = sbase + col;                     // <=127, even
            float c20 = c2p[col];
            float c21 = c2p[col + 1];
            *(float2*)&rel[(qw + lr) * LDR + slot] =
                make_float2(acc1[jf][0] + c20, acc1[jf][1] + c21);
            *(float2*)&rel[(qw + 8 + lr) * LDR + slot] =
                make_float2(acc1[jf][2] + c20, acc1[jf][3] + c21);
        }
        PAIR_BAR(pid);     // rel rows of this q-group complete (pair-local)

        // ---- logits = content + c1 + shifted rel; row max ----
        const float* c1p = c1base + j0;
        float lg[4][4];
        float mx_lo = -1e30f, mx_hi = -1e30f;
#pragma unroll
        for (int jf = 0; jf < 4; jf++) {
            int jl = nhalf * 32 + jf * 8 + 2 * lc;
            float2 c1v = *(const float2*)(c1p + jl);
            int d0 = sbase + jl - (qw + lr);            // may be negative
            int d1 = d0 - 8;
            lg[jf][0] = acc2[jf][0] + c1v.x + rel[(qw + lr) * LDR + (d0 & 127)];
            lg[jf][1] = acc2[jf][1] + c1v.y + rel[(qw + lr) * LDR + ((d0 + 1) & 127)];
            lg[jf][2] = acc2[jf][2] + c1v.x + rel[(qw + 8 + lr) * LDR + (d1 & 127)];
            lg[jf][3] = acc2[jf][3] + c1v.y + rel[(qw + 8 + lr) * LDR + ((d1 + 1) & 127)];
            mx_lo = fmaxf(mx_lo, fmaxf(lg[jf][0], lg[jf][1]));
            mx_hi = fmaxf(mx_hi, fmaxf(lg[jf][2], lg[jf][3]));
        }
        mx_lo = fmaxf(mx_lo, __shfl_xor_sync(0xffffffffu, mx_lo, 1));
        mx_lo = fmaxf(mx_lo, __shfl_xor_sync(0xffffffffu, mx_lo, 2));
        mx_hi = fmaxf(mx_hi, __shfl_xor_sync(0xffffffffu, mx_hi, 1));
        mx_hi = fmaxf(mx_hi, __shfl_xor_sync(0xffffffffu, mx_hi, 2));
        if (lc == 0) {
            smx[nhalf * 64 + qw + lr] = mx_lo;
            smx[nhalf * 64 + qw + 8 + lr] = mx_hi;
        }
        PAIR_BAR(pid);
        mx_lo = fmaxf(mx_lo, smx[(1 - nhalf) * 64 + qw + lr]);
        mx_hi = fmaxf(mx_hi, smx[(1 - nhalf) * 64 + qw + 8 + lr]);

        float mn_lo = fmaxf(m_lo, mx_lo), mn_hi = fmaxf(m_hi, mx_hi);
        float sc_lo = __expf(m_lo - mn_lo), sc_hi = __expf(m_hi - mn_hi);
        m_lo = mn_lo; m_hi = mn_hi;
        float su_lo = 0.f, su_hi = 0.f;
        float pv[4][4];
#pragma unroll
        for (int jf = 0; jf < 4; jf++) {
            pv[jf][0] = __expf(lg[jf][0] - mn_lo);
            pv[jf][1] = __expf(lg[jf][1] - mn_lo);
            pv[jf][2] = __expf(lg[jf][2] - mn_hi);
            pv[jf][3] = __expf(lg[jf][3] - mn_hi);
            su_lo += pv[jf][0] + pv[jf][1];
            su_hi += pv[jf][2] + pv[jf][3];
        }
        su_lo += __shfl_xor_sync(0xffffffffu, su_lo, 1);
        su_lo += __shfl_xor_sync(0xffffffffu, su_lo, 2);
        su_hi += __shfl_xor_sync(0xffffffffu, su_hi, 1);
        su_hi += __shfl_xor_sync(0xffffffffu, su_hi, 2);
        if (lc == 0) {
            sms[nhalf * 64 + qw + lr] = su_lo;
            sms[nhalf * 64 + qw + 8 + lr] = su_hi;
        }
#pragma unroll
        for (int jf = 0; jf < 4; jf++) {
            int jl = nhalf * 32 + jf * 8 + 2 * lc;
            *(uint2*)&Ps[(qw + lr) * LDK + jl] =
                make_uint2(f2tf(pv[jf][0]), f2tf(pv[jf][1]));
            *(uint2*)&Ps[(qw + 8 + lr) * LDK + jl] =
                make_uint2(f2tf(pv[jf][2]), f2tf(pv[jf][3]));
        }
        MBAR_WAIT(mbVcur, (jt >> 1) & 1);   // V[jt] (issued one iter ahead)
        PAIR_BAR(pid);
        l_lo = l_lo * sc_lo + su_lo + sms[(1 - nhalf) * 64 + qw + lr];
        l_hi = l_hi * sc_hi + su_hi + sms[(1 - nhalf) * 64 + qw + 8 + lr];

#pragma unroll
        for (int nf = 0; nf < 12; nf++) {
            accO[nf][0] *= sc_lo; accO[nf][1] *= sc_lo;
            accO[nf][2] *= sc_hi; accO[nf][3] *= sc_hi;
        }
#pragma unroll
        for (int s = 0; s < 8; s++) {
            int kb = s * 8;
            unsigned afr[4];
            afr[0] = __float_as_uint(Ps[(qw + lr) * LDK + kb + lc]);
            afr[1] = __float_as_uint(Ps[(qw + 8 + lr) * LDK + kb + lc]);
            afr[2] = __float_as_uint(Ps[(qw + lr) * LDK + kb + 4 + lc]);
            afr[3] = __float_as_uint(Ps[(qw + 8 + lr) * LDK + kb + 4 + lc]);
#pragma unroll
            for (int nf = 0; nf < 12; nf++) {
                int cc = nhalf * 96 + nf * 8 + lr;
                unsigned bfr[2];
                bfr[0] = __float_as_uint(Vs[(kb + lc) * LDV + cc]);
                bfr[1] = __float_as_uint(Vs[(kb + 4 + lc) * LDV + cc]);
                mma8(accO[nf], afr, bfr);
            }
        }
    }

    float il_lo = 1.0f / l_lo, il_hi = 1.0f / l_hi;
    float* og_lo = g_att + (size_t)(b * Tn + q0 + qw + lr) * HV + h * Vn;
    float* og_hi = og_lo + (size_t)8 * HV;
#pragma unroll
    for (int nf = 0; nf < 12; nf++) {
        int cc = nhalf * 96 + nf * 8 + 2 * lc;
        *(float2*)(og_lo + cc) = make_float2(accO[nf][0] * il_lo, accO[nf][1] * il_lo);
        *(float2*)(og_hi + cc) = make_float2(accO[nf][2] * il_hi, accO[nf][3] * il_hi);
    }
}

// ---------------- host orchestration ------------------------------------------
extern "C" void kernel_launch(void* const* d_in, const int* in_sizes, int n_in,
                              void* d_out, int out_size)
{
    (void)in_sizes; (void)n_in; (void)out_size;
    const float* x    = (const float*)d_in[0];
    const float* Wq   = (const float*)d_in[1];
    const float* Wk   = (const float*)d_in[2];
    const float* Wv   = (const float*)d_in[3];
    const float* Wrk  = (const float*)d_in[4];
    const float* Wemb = (const float*)d_in[5];
    const float* rwb  = (const float*)d_in[6];
    const float* rrb  = (const float*)d_in[7];
    float* out = (float*)d_out;

    float *emb, *rkp, *att;
    cudaGetSymbolAddress((void**)&emb, g_emb);
    cudaGetSymbolAddress((void**)&rkp, g_rkp);
    cudaGetSymbolAddress((void**)&att, g_att);

    cudaFuncSetAttribute(flash_kernel, cudaFuncAttributeMaxDynamicSharedMemorySize, SM_BYTES);

    // 1) positional features
    int n1 = Rn * 96;
    pos_fill<<<(n1 + 255) / 256, 256>>>();
    pos_fin<<<(n1 + 255) / 256, 256>>>();

    // 2) r_k = emb @ Wrk -> head-major padded g_rkp
    tgemm_kernel<3, 64, 68, Rn><<<dim3(4, 24), 256>>>(
        emb, Wrk, rkp, Rn, HK, 192, 192, HK, 0, 1.0f);

    // 3) fused q/k/v projections
    qkv_kernel<<<dim3(20, 24), 256>>>(x, Wq, Wk, Wv);

    // 4) rank-1 bias terms
    bias2_kernel<<<3072 + Rn, 64>>>(rwb, rrb);

    // 5) fused attention (rolling-rel + double-buffered V)
    flash_kernel<<<dim3(24, 16), 256, SM_BYTES>>>();

    // 6) out = att @ Wemb
    tgemm_kernel<0, 1, 1, 1><<<dim3(12, 24), 256>>>(
        att, Wemb, out, Bn * Tn, Dn, HV, HV, Dn, Dn, 1.0f);
}